// round 4
// baseline (speedup 1.0000x reference)
#include <cuda_runtime.h>
#include <cstdint>

// Problem constants
#define PB   2
#define PS   2048
#define PD   2048
#define PH   16
#define PHKV 4
#define PDH  128
#define PKVD (PHKV * PDH)   // 512

// ---------------------------------------------------------------------------
// Scratch (device globals: no allocations allowed)
// ---------------------------------------------------------------------------
__device__ float g_Q[(size_t)PB * PS * PD];     // 33.5 MB
__device__ float g_K[(size_t)PB * PS * PKVD];   //  8.4 MB
__device__ float g_V[(size_t)PB * PS * PKVD];   //  8.4 MB
__device__ float g_ctx[(size_t)PB * PS * PD];   // 33.5 MB

// ---------------------------------------------------------------------------
// SGEMM: C[M,N] = A[M,K] @ B[K,N], all row-major, fp32.
// 128x128 tile, BK=16, 256 threads, 8x8 per thread, double-buffered smem.
// M,N,K assumed multiples of tile sizes (true for all 4 calls).
// ---------------------------------------------------------------------------
__global__ __launch_bounds__(256, 2)
void sgemm128(const float* __restrict__ A, const float* __restrict__ B,
              float* __restrict__ C, int M, int N, int K)
{
    __shared__ float As[2][16][132];   // transposed A tile, padded
    __shared__ float Bs[2][16][128];

    const int tid = threadIdx.x;
    const int tx  = tid & 15;
    const int ty  = tid >> 4;
    const int m0  = blockIdx.y * 128;
    const int n0  = blockIdx.x * 128;

    // Global load mapping
    const int arow = tid >> 1;        // 0..127
    const int acol = (tid & 1) * 8;   // 0 or 8
    const int brow = tid >> 4;        // 0..15
    const int bcol = (tid & 15) * 8;

    const float* Ap = A + (size_t)(m0 + arow) * K + acol;
    const float* Bp = B + (size_t)brow * N + n0 + bcol;

    // Prologue: load tile 0
    float4 ar0 = *(const float4*)(Ap);
    float4 ar1 = *(const float4*)(Ap + 4);
    float4 br0 = *(const float4*)(Bp);
    float4 br1 = *(const float4*)(Bp + 4);

    As[0][acol + 0][arow] = ar0.x; As[0][acol + 1][arow] = ar0.y;
    As[0][acol + 2][arow] = ar0.z; As[0][acol + 3][arow] = ar0.w;
    As[0][acol + 4][arow] = ar1.x; As[0][acol + 5][arow] = ar1.y;
    As[0][acol + 6][arow] = ar1.z; As[0][acol + 7][arow] = ar1.w;
    *(float4*)&Bs[0][brow][bcol]     = br0;
    *(float4*)&Bs[0][brow][bcol + 4] = br1;
    __syncthreads();

    float acc[8][8];
    #pragma unroll
    for (int i = 0; i < 8; i++)
        #pragma unroll
        for (int j = 0; j < 8; j++) acc[i][j] = 0.0f;

    int buf = 0;
    for (int k0 = 0; k0 < K; k0 += 16) {
        const bool hasNext = (k0 + 16) < K;
        if (hasNext) {
            const float* Ap2 = Ap + (k0 + 16);
            const float* Bp2 = Bp + (size_t)(k0 + 16) * N;
            ar0 = *(const float4*)(Ap2);
            ar1 = *(const float4*)(Ap2 + 4);
            br0 = *(const float4*)(Bp2);
            br1 = *(const float4*)(Bp2 + 4);
        }

        #pragma unroll
        for (int kk = 0; kk < 16; kk++) {
            float a[8], b[8];
            *(float4*)(a)     = *(const float4*)&As[buf][kk][ty * 8];
            *(float4*)(a + 4) = *(const float4*)&As[buf][kk][ty * 8 + 4];
            *(float4*)(b)     = *(const float4*)&Bs[buf][kk][tx * 8];
            *(float4*)(b + 4) = *(const float4*)&Bs[buf][kk][tx * 8 + 4];
            #pragma unroll
            for (int i = 0; i < 8; i++)
                #pragma unroll
                for (int j = 0; j < 8; j++)
                    acc[i][j] = fmaf(a[i], b[j], acc[i][j]);
        }

        if (hasNext) {
            const int nb = buf ^ 1;
            As[nb][acol + 0][arow] = ar0.x; As[nb][acol + 1][arow] = ar0.y;
            As[nb][acol + 2][arow] = ar0.z; As[nb][acol + 3][arow] = ar0.w;
            As[nb][acol + 4][arow] = ar1.x; As[nb][acol + 5][arow] = ar1.y;
            As[nb][acol + 6][arow] = ar1.z; As[nb][acol + 7][arow] = ar1.w;
            *(float4*)&Bs[nb][brow][bcol]     = br0;
            *(float4*)&Bs[nb][brow][bcol + 4] = br1;
        }
        __syncthreads();
        buf ^= 1;
    }

    float* Cp = C + (size_t)(m0 + ty * 8) * N + n0 + tx * 8;
    #pragma unroll
    for (int i = 0; i < 8; i++) {
        float4 c0 = make_float4(acc[i][0], acc[i][1], acc[i][2], acc[i][3]);
        float4 c1 = make_float4(acc[i][4], acc[i][5], acc[i][6], acc[i][7]);
        *(float4*)(Cp + (size_t)i * N)     = c0;
        *(float4*)(Cp + (size_t)i * N + 4) = c1;
    }
}

// ---------------------------------------------------------------------------
// Fused GQA flash attention.
// Grid: (S/64 q-tiles, H heads, B batch). 256 threads.
// Q head h reads cols [h*128, h*128+128) of g_Q; KV group g = h/4 reads
// cols [g*128, ...) of g_K/g_V. Online softmax, O accumulated in registers.
// Dynamic smem: sQT[128][64] | sKT[128][64] | sV[64][132] | sP[64][68]
// ---------------------------------------------------------------------------
#define AT_SMEM_FLOATS (128*64 + 128*64 + 64*132 + 64*68)   // 29184
#define AT_SMEM_BYTES  (AT_SMEM_FLOATS * 4)                 // 116736

__global__ __launch_bounds__(256, 1)
void gqa_attention(const float* __restrict__ Q, const float* __restrict__ Kp,
                   const float* __restrict__ Vp, const int* __restrict__ mask,
                   float* __restrict__ ctx)
{
    extern __shared__ float smem[];
    float* sQT = smem;                   // [128][64]  d-major
    float* sKT = sQT + 128 * 64;         // [128][64]  d-major
    float* sV  = sKT + 128 * 64;         // [64][132]  row-major, padded
    float* sP  = sV  + 64 * 132;         // [64][68]   padded

    const int tid = threadIdx.x;
    const int tx  = tid & 15;
    const int ty  = tid >> 4;
    const int q0  = blockIdx.x * 64;
    const int h   = blockIdx.y;
    const int b   = blockIdx.z;
    const int g   = h >> 2;

    const float scale = 0.08838834764831845f;   // 1/sqrt(128)

    // ---- Load Q tile transposed (once) ----
    {
        const int r  = tid & 63;
        const int cb = (tid >> 6) * 32;
        const float* gq = Q + ((size_t)(b * PS + q0 + r)) * PD + h * PDH + cb;
        #pragma unroll
        for (int i = 0; i < 8; i++) {
            float4 v = *(const float4*)(gq + 4 * i);
            const int c = cb + 4 * i;
            sQT[(c + 0) * 64 + r] = v.x;
            sQT[(c + 1) * 64 + r] = v.y;
            sQT[(c + 2) * 64 + r] = v.z;
            sQT[(c + 3) * 64 + r] = v.w;
        }
    }

    float o[4][8];
    #pragma unroll
    for (int i = 0; i < 4; i++)
        #pragma unroll
        for (int j = 0; j < 8; j++) o[i][j] = 0.0f;
    float mrow[4], lrow[4];
    #pragma unroll
    for (int i = 0; i < 4; i++) { mrow[i] = -3.0e38f; lrow[i] = 0.0f; }

    for (int kt = 0; kt < PS / 64; kt++) {
        const int k0 = kt * 64;
        __syncthreads();   // previous iteration's reads of sKT/sV/sP done

        // ---- Load K tile (transposed) + V tile ----
        {
            const int r  = tid & 63;
            const int cb = (tid >> 6) * 32;
            const float* gk = Kp + ((size_t)(b * PS + k0 + r)) * PKVD + g * PDH + cb;
            #pragma unroll
            for (int i = 0; i < 8; i++) {
                float4 v = *(const float4*)(gk + 4 * i);
                const int c = cb + 4 * i;
                sKT[(c + 0) * 64 + r] = v.x;
                sKT[(c + 1) * 64 + r] = v.y;
                sKT[(c + 2) * 64 + r] = v.z;
                sKT[(c + 3) * 64 + r] = v.w;
            }
            const int vr  = tid >> 2;
            const int vcb = (tid & 3) * 32;
            const float* gv = Vp + ((size_t)(b * PS + k0 + vr)) * PKVD + g * PDH + vcb;
            float* dv = sV + vr * 132 + vcb;
            #pragma unroll
            for (int i = 0; i < 8; i++)
                *(float4*)(dv + 4 * i) = *(const float4*)(gv + 4 * i);
        }
        __syncthreads();

        // ---- S = Q K^T (each thread: 4x4 block at rows ty*4, cols tx*4) ----
        float acc[4][4];
        #pragma unroll
        for (int i = 0; i < 4; i++)
            #pragma unroll
            for (int j = 0; j < 4; j++) acc[i][j] = 0.0f;

        #pragma unroll 8
        for (int d = 0; d < 128; d++) {
            const float4 q4 = *(const float4*)(sQT + d * 64 + (ty << 2));
            const float4 k4 = *(const float4*)(sKT + d * 64 + (tx << 2));
            const float qv[4] = {q4.x, q4.y, q4.z, q4.w};
            const float kv[4] = {k4.x, k4.y, k4.z, k4.w};
            #pragma unroll
            for (int i = 0; i < 4; i++)
                #pragma unroll
                for (int j = 0; j < 4; j++)
                    acc[i][j] = fmaf(qv[i], kv[j], acc[i][j]);
        }

        // ---- mask + scale, online softmax ----
        #pragma unroll
        for (int i = 0; i < 4; i++) {
            const int4 mv = *(const int4*)(mask +
                ((size_t)(b * PS + q0 + ty * 4 + i)) * PS + k0 + tx * 4);
            float s0 = mv.x ? acc[i][0] * scale : -1e9f;
            float s1 = mv.y ? acc[i][1] * scale : -1e9f;
            float s2 = mv.z ? acc[i][2] * scale : -1e9f;
            float s3 = mv.w ? acc[i][3] * scale : -1e9f;

            float tmax = fmaxf(fmaxf(s0, s1), fmaxf(s2, s3));
            #pragma unroll
            for (int off = 8; off > 0; off >>= 1)
                tmax = fmaxf(tmax, __shfl_xor_sync(0xffffffffu, tmax, off, 16));

            const float mnew  = fmaxf(mrow[i], tmax);
            const float alpha = __expf(mrow[i] - mnew);
            const float p0 = __expf(s0 - mnew);
            const float p1 = __expf(s1 - mnew);
            const float p2 = __expf(s2 - mnew);
            const float p3 = __expf(s3 - mnew);
            float rs = p0 + p1 + p2 + p3;
            #pragma unroll
            for (int off = 8; off > 0; off >>= 1)
                rs += __shfl_xor_sync(0xffffffffu, rs, off, 16);

            lrow[i] = lrow[i] * alpha + rs;
            mrow[i] = mnew;
            *(float4*)(sP + (ty * 4 + i) * 68 + tx * 4) = make_float4(p0, p1, p2, p3);
            #pragma unroll
            for (int j = 0; j < 8; j++) o[i][j] *= alpha;
        }
        __syncthreads();   // sP visible to all

        // ---- O += P @ V (each thread: rows ty*4.., cols tx*8..) ----
        #pragma unroll 4
        for (int k = 0; k < 64; k++) {
            const float4 va = *(const float4*)(sV + k * 132 + (tx << 3));
            const float4 vb = *(const float4*)(sV + k * 132 + (tx << 3) + 4);
            const float vv[8] = {va.x, va.y, va.z, va.w, vb.x, vb.y, vb.z, vb.w};
            #pragma unroll
            for (int i = 0; i < 4; i++) {
                const float p = sP[(ty * 4 + i) * 68 + k];
                #pragma unroll
                for (int j = 0; j < 8; j++)
                    o[i][j] = fmaf(p, vv[j], o[i][j]);
            }
        }
    }

    // ---- Epilogue: normalize and write ctx ----
    #pragma unroll
    for (int i = 0; i < 4; i++) {
        const float inv = 1.0f / lrow[i];
        float* cp = ctx + ((size_t)(b * PS + q0 + ty * 4 + i)) * PD + h * PDH + tx * 8;
        *(float4*)(cp)     = make_float4(o[i][0] * inv, o[i][1] * inv,
                                         o[i][2] * inv, o[i][3] * inv);
        *(float4*)(cp + 4) = make_float4(o[i][4] * inv, o[i][5] * inv,
                                         o[i][6] * inv, o[i][7] * inv);
    }
}

// ---------------------------------------------------------------------------
// Launch
// ---------------------------------------------------------------------------
extern "C" void kernel_launch(void* const* d_in, const int* in_sizes, int n_in,
                              void* d_out, int out_size)
{
    (void)in_sizes; (void)n_in; (void)out_size;
    const float* query = (const float*)d_in[0];
    const float* key   = (const float*)d_in[1];
    const float* value = (const float*)d_in[2];
    const int*   mask  = (const int*)  d_in[3];
    const float* Wq    = (const float*)d_in[4];
    const float* Wk    = (const float*)d_in[5];
    const float* Wv    = (const float*)d_in[6];
    const float* Wo    = (const float*)d_in[7];
    float* out = (float*)d_out;

    float *pQ, *pK, *pV, *pCtx;
    cudaGetSymbolAddress((void**)&pQ,   g_Q);
    cudaGetSymbolAddress((void**)&pK,   g_K);
    cudaGetSymbolAddress((void**)&pV,   g_V);
    cudaGetSymbolAddress((void**)&pCtx, g_ctx);

    cudaFuncSetAttribute(gqa_attention,
                         cudaFuncAttributeMaxDynamicSharedMemorySize,
                         AT_SMEM_BYTES);

    const int M = PB * PS;   // 4096
    dim3 blk(256);

    // Projections
    sgemm128<<<dim3(PD / 128,   M / 128), blk>>>(query, Wq, pQ, M, PD,   PD);
    sgemm128<<<dim3(PKVD / 128, M / 128), blk>>>(key,   Wk, pK, M, PKVD, PD);
    sgemm128<<<dim3(PKVD / 128, M / 128), blk>>>(value, Wv, pV, M, PKVD, PD);

    // Fused attention
    gqa_attention<<<dim3(PS / 64, PH, PB), blk, AT_SMEM_BYTES>>>(pQ, pK, pV, mask, pCtx);

    // Output projection
    sgemm128<<<dim3(PD / 128, M / 128), blk>>>(pCtx, Wo, out, M, PD, PD);
}

// round 5
// speedup vs baseline: 1.0598x; 1.0598x over previous
#include <cuda_runtime.h>
#include <cstdint>

// Problem constants
#define PB   2
#define PS   2048
#define PD   2048
#define PH   16
#define PHKV 4
#define PDH  128
#define PKVD (PHKV * PDH)   // 512

// ---------------------------------------------------------------------------
// Scratch (device globals: no allocations allowed)
// ---------------------------------------------------------------------------
__device__ float g_Q[(size_t)PB * PS * PD];     // 33.5 MB
__device__ float g_K[(size_t)PB * PS * PKVD];   //  8.4 MB
__device__ float g_V[(size_t)PB * PS * PKVD];   //  8.4 MB
__device__ float g_ctx[(size_t)PB * PS * PD];   // 33.5 MB

// ---------------------------------------------------------------------------
// TF32 helpers
// ---------------------------------------------------------------------------
__device__ __forceinline__ uint32_t f2tf32(float f) {
    uint32_t u;
    asm("cvt.rna.tf32.f32 %0, %1;" : "=r"(u) : "f"(f));
    return u;
}

__device__ __forceinline__ void mma_tf32(float* c, const uint32_t* a, const uint32_t* b) {
    asm volatile(
        "mma.sync.aligned.m16n8k8.row.col.f32.tf32.tf32.f32 "
        "{%0,%1,%2,%3}, {%4,%5,%6,%7}, {%8,%9}, {%0,%1,%2,%3};"
        : "+f"(c[0]), "+f"(c[1]), "+f"(c[2]), "+f"(c[3])
        : "r"(a[0]), "r"(a[1]), "r"(a[2]), "r"(a[3]),
          "r"(b[0]), "r"(b[1]));
}

// ---------------------------------------------------------------------------
// TF32 tensor-core GEMM (3xTF32 for fp32-level accuracy):
// C[M,N] = A[M,K] @ B[K,N], all row-major fp32.
// 128x128 block tile, BK=16, 256 threads (8 warps, 2x4), warp tile 64x32.
// Each warp: 4 (m) x 4 (n) m16n8k8 tiles; 3 HW mma per logical mma.
// Double-buffered smem, register prefetch of next global tile.
// ---------------------------------------------------------------------------
__global__ __launch_bounds__(256, 2)
void gemm_tf32(const float* __restrict__ A, const float* __restrict__ B,
               float* __restrict__ C, int M, int N, int K)
{
    __shared__ float As[2][16][132];   // A tile transposed: As[k][m], padded
    __shared__ float Bs[2][16][132];   // B tile:            Bs[k][n], padded

    const int tid  = threadIdx.x;
    const int lane = tid & 31;
    const int wid  = tid >> 5;
    const int g    = lane >> 2;     // 0..7
    const int t4   = lane & 3;      // 0..3

    const int warp_m = wid >> 2;    // 0..1 -> 64 rows
    const int warp_n = wid & 3;     // 0..3 -> 32 cols
    const int rmBase = warp_m * 64;
    const int cnBase = warp_n * 32;

    const int m0 = blockIdx.y * 128;
    const int n0 = blockIdx.x * 128;

    // Global load mapping (each thread: 8 floats of A, 8 of B per tile)
    const int arow = tid >> 1;        // 0..127
    const int acol = (tid & 1) * 8;   // 0 or 8
    const int brow = tid >> 4;        // 0..15
    const int bcol = (tid & 15) * 8;

    const float* Ap = A + (size_t)(m0 + arow) * K + acol;
    const float* Bp = B + (size_t)brow * N + n0 + bcol;

    // Prologue: load tile 0
    float4 ar0 = *(const float4*)(Ap);
    float4 ar1 = *(const float4*)(Ap + 4);
    float4 br0 = *(const float4*)(Bp);
    float4 br1 = *(const float4*)(Bp + 4);

    As[0][acol + 0][arow] = ar0.x; As[0][acol + 1][arow] = ar0.y;
    As[0][acol + 2][arow] = ar0.z; As[0][acol + 3][arow] = ar0.w;
    As[0][acol + 4][arow] = ar1.x; As[0][acol + 5][arow] = ar1.y;
    As[0][acol + 6][arow] = ar1.z; As[0][acol + 7][arow] = ar1.w;
    *(float4*)&Bs[0][brow][bcol]     = br0;
    *(float4*)&Bs[0][brow][bcol + 4] = br1;
    __syncthreads();

    float acc[4][4][4];
    #pragma unroll
    for (int mt = 0; mt < 4; mt++)
        #pragma unroll
        for (int nt = 0; nt < 4; nt++)
            #pragma unroll
            for (int j = 0; j < 4; j++) acc[mt][nt][j] = 0.0f;

    int buf = 0;
    for (int k0 = 0; k0 < K; k0 += 16) {
        const bool hasNext = (k0 + 16) < K;
        if (hasNext) {
            const float* Ap2 = Ap + (k0 + 16);
            const float* Bp2 = Bp + (size_t)(k0 + 16) * N;
            ar0 = *(const float4*)(Ap2);
            ar1 = *(const float4*)(Ap2 + 4);
            br0 = *(const float4*)(Bp2);
            br1 = *(const float4*)(Bp2 + 4);
        }

        #pragma unroll
        for (int ks = 0; ks < 2; ks++) {
            const int kb = ks * 8;

            // ---- B fragments (col-major k x n): b0=(k=t4, n), b1=(k=t4+4, n)
            uint32_t bhi[4][2], blo[4][2];
            #pragma unroll
            for (int nt = 0; nt < 4; nt++) {
                #pragma unroll
                for (int j = 0; j < 2; j++) {
                    float f = Bs[buf][kb + t4 + j * 4][cnBase + nt * 8 + g];
                    uint32_t h = f2tf32(f);
                    bhi[nt][j] = h;
                    blo[nt][j] = f2tf32(f - __uint_as_float(h));
                }
            }

            // ---- A fragments + mma
            #pragma unroll
            for (int mt = 0; mt < 4; mt++) {
                uint32_t ahi[4], alo[4];
                // a0=(g,t4) a1=(g+8,t4) a2=(g,t4+4) a3=(g+8,t4+4)
                #pragma unroll
                for (int j = 0; j < 4; j++) {
                    const int rr = rmBase + mt * 16 + g + (j & 1) * 8;
                    const int kk = kb + t4 + (j >> 1) * 4;
                    float f = As[buf][kk][rr];
                    uint32_t h = f2tf32(f);
                    ahi[j] = h;
                    alo[j] = f2tf32(f - __uint_as_float(h));
                }
                #pragma unroll
                for (int nt = 0; nt < 4; nt++) {
                    mma_tf32(acc[mt][nt], ahi, blo[nt]);  // small terms first
                    mma_tf32(acc[mt][nt], alo, bhi[nt]);
                    mma_tf32(acc[mt][nt], ahi, bhi[nt]);
                }
            }
        }

        if (hasNext) {
            const int nb = buf ^ 1;
            As[nb][acol + 0][arow] = ar0.x; As[nb][acol + 1][arow] = ar0.y;
            As[nb][acol + 2][arow] = ar0.z; As[nb][acol + 3][arow] = ar0.w;
            As[nb][acol + 4][arow] = ar1.x; As[nb][acol + 5][arow] = ar1.y;
            As[nb][acol + 6][arow] = ar1.z; As[nb][acol + 7][arow] = ar1.w;
            *(float4*)&Bs[nb][brow][bcol]     = br0;
            *(float4*)&Bs[nb][brow][bcol + 4] = br1;
        }
        __syncthreads();
        buf ^= 1;
    }

    // ---- Epilogue: c0=(g, 2*t4), c1=(g, 2*t4+1), c2=(g+8, 2*t4), c3=(g+8, 2*t4+1)
    #pragma unroll
    for (int mt = 0; mt < 4; mt++) {
        #pragma unroll
        for (int nt = 0; nt < 4; nt++) {
            const int row = m0 + rmBase + mt * 16 + g;
            const int col = n0 + cnBase + nt * 8 + 2 * t4;
            float* Cp = C + (size_t)row * N + col;
            *(float2*)(Cp)               = make_float2(acc[mt][nt][0], acc[mt][nt][1]);
            *(float2*)(Cp + (size_t)8*N) = make_float2(acc[mt][nt][2], acc[mt][nt][3]);
        }
    }
}

// ---------------------------------------------------------------------------
// Fused GQA flash attention (unchanged from passing R4 version).
// Grid: (S/64 q-tiles, H heads, B batch). 256 threads.
// ---------------------------------------------------------------------------
#define AT_SMEM_FLOATS (128*64 + 128*64 + 64*132 + 64*68)   // 29184
#define AT_SMEM_BYTES  (AT_SMEM_FLOATS * 4)                 // 116736

__global__ __launch_bounds__(256, 1)
void gqa_attention(const float* __restrict__ Q, const float* __restrict__ Kp,
                   const float* __restrict__ Vp, const int* __restrict__ mask,
                   float* __restrict__ ctx)
{
    extern __shared__ float smem[];
    float* sQT = smem;                   // [128][64]  d-major
    float* sKT = sQT + 128 * 64;         // [128][64]  d-major
    float* sV  = sKT + 128 * 64;         // [64][132]  row-major, padded
    float* sP  = sV  + 64 * 132;         // [64][68]   padded

    const int tid = threadIdx.x;
    const int tx  = tid & 15;
    const int ty  = tid >> 4;
    const int q0  = blockIdx.x * 64;
    const int h   = blockIdx.y;
    const int b   = blockIdx.z;
    const int g   = h >> 2;

    const float scale = 0.08838834764831845f;   // 1/sqrt(128)

    // ---- Load Q tile transposed (once) ----
    {
        const int r  = tid & 63;
        const int cb = (tid >> 6) * 32;
        const float* gq = Q + ((size_t)(b * PS + q0 + r)) * PD + h * PDH + cb;
        #pragma unroll
        for (int i = 0; i < 8; i++) {
            float4 v = *(const float4*)(gq + 4 * i);
            const int c = cb + 4 * i;
            sQT[(c + 0) * 64 + r] = v.x;
            sQT[(c + 1) * 64 + r] = v.y;
            sQT[(c + 2) * 64 + r] = v.z;
            sQT[(c + 3) * 64 + r] = v.w;
        }
    }

    float o[4][8];
    #pragma unroll
    for (int i = 0; i < 4; i++)
        #pragma unroll
        for (int j = 0; j < 8; j++) o[i][j] = 0.0f;
    float mrow[4], lrow[4];
    #pragma unroll
    for (int i = 0; i < 4; i++) { mrow[i] = -3.0e38f; lrow[i] = 0.0f; }

    for (int kt = 0; kt < PS / 64; kt++) {
        const int k0 = kt * 64;
        __syncthreads();   // previous iteration's reads of sKT/sV/sP done

        // ---- Load K tile (transposed) + V tile ----
        {
            const int r  = tid & 63;
            const int cb = (tid >> 6) * 32;
            const float* gk = Kp + ((size_t)(b * PS + k0 + r)) * PKVD + g * PDH + cb;
            #pragma unroll
            for (int i = 0; i < 8; i++) {
                float4 v = *(const float4*)(gk + 4 * i);
                const int c = cb + 4 * i;
                sKT[(c + 0) * 64 + r] = v.x;
                sKT[(c + 1) * 64 + r] = v.y;
                sKT[(c + 2) * 64 + r] = v.z;
                sKT[(c + 3) * 64 + r] = v.w;
            }
            const int vr  = tid >> 2;
            const int vcb = (tid & 3) * 32;
            const float* gv = Vp + ((size_t)(b * PS + k0 + vr)) * PKVD + g * PDH + vcb;
            float* dv = sV + vr * 132 + vcb;
            #pragma unroll
            for (int i = 0; i < 8; i++)
                *(float4*)(dv + 4 * i) = *(const float4*)(gv + 4 * i);
        }
        __syncthreads();

        // ---- S = Q K^T (each thread: 4x4 block at rows ty*4, cols tx*4) ----
        float acc[4][4];
        #pragma unroll
        for (int i = 0; i < 4; i++)
            #pragma unroll
            for (int j = 0; j < 4; j++) acc[i][j] = 0.0f;

        #pragma unroll 8
        for (int d = 0; d < 128; d++) {
            const float4 q4 = *(const float4*)(sQT + d * 64 + (ty << 2));
            const float4 k4 = *(const float4*)(sKT + d * 64 + (tx << 2));
            const float qv[4] = {q4.x, q4.y, q4.z, q4.w};
            const float kv[4] = {k4.x, k4.y, k4.z, k4.w};
            #pragma unroll
            for (int i = 0; i < 4; i++)
                #pragma unroll
                for (int j = 0; j < 4; j++)
                    acc[i][j] = fmaf(qv[i], kv[j], acc[i][j]);
        }

        // ---- mask + scale, online softmax ----
        #pragma unroll
        for (int i = 0; i < 4; i++) {
            const int4 mv = *(const int4*)(mask +
                ((size_t)(b * PS + q0 + ty * 4 + i)) * PS + k0 + tx * 4);
            float s0 = mv.x ? acc[i][0] * scale : -1e9f;
            float s1 = mv.y ? acc[i][1] * scale : -1e9f;
            float s2 = mv.z ? acc[i][2] * scale : -1e9f;
            float s3 = mv.w ? acc[i][3] * scale : -1e9f;

            float tmax = fmaxf(fmaxf(s0, s1), fmaxf(s2, s3));
            #pragma unroll
            for (int off = 8; off > 0; off >>= 1)
                tmax = fmaxf(tmax, __shfl_xor_sync(0xffffffffu, tmax, off, 16));

            const float mnew  = fmaxf(mrow[i], tmax);
            const float alpha = __expf(mrow[i] - mnew);
            const float p0 = __expf(s0 - mnew);
            const float p1 = __expf(s1 - mnew);
            const float p2 = __expf(s2 - mnew);
            const float p3 = __expf(s3 - mnew);
            float rs = p0 + p1 + p2 + p3;
            #pragma unroll
            for (int off = 8; off > 0; off >>= 1)
                rs += __shfl_xor_sync(0xffffffffu, rs, off, 16);

            lrow[i] = lrow[i] * alpha + rs;
            mrow[i] = mnew;
            *(float4*)(sP + (ty * 4 + i) * 68 + tx * 4) = make_float4(p0, p1, p2, p3);
            #pragma unroll
            for (int j = 0; j < 8; j++) o[i][j] *= alpha;
        }
        __syncthreads();   // sP visible to all

        // ---- O += P @ V (each thread: rows ty*4.., cols tx*8..) ----
        #pragma unroll 4
        for (int k = 0; k < 64; k++) {
            const float4 va = *(const float4*)(sV + k * 132 + (tx << 3));
            const float4 vb = *(const float4*)(sV + k * 132 + (tx << 3) + 4);
            const float vv[8] = {va.x, va.y, va.z, va.w, vb.x, vb.y, vb.z, vb.w};
            #pragma unroll
            for (int i = 0; i < 4; i++) {
                const float p = sP[(ty * 4 + i) * 68 + k];
                #pragma unroll
                for (int j = 0; j < 8; j++)
                    o[i][j] = fmaf(p, vv[j], o[i][j]);
            }
        }
    }

    // ---- Epilogue: normalize and write ctx ----
    #pragma unroll
    for (int i = 0; i < 4; i++) {
        const float inv = 1.0f / lrow[i];
        float* cp = ctx + ((size_t)(b * PS + q0 + ty * 4 + i)) * PD + h * PDH + tx * 8;
        *(float4*)(cp)     = make_float4(o[i][0] * inv, o[i][1] * inv,
                                         o[i][2] * inv, o[i][3] * inv);
        *(float4*)(cp + 4) = make_float4(o[i][4] * inv, o[i][5] * inv,
                                         o[i][6] * inv, o[i][7] * inv);
    }
}

// ---------------------------------------------------------------------------
// Launch
// ---------------------------------------------------------------------------
extern "C" void kernel_launch(void* const* d_in, const int* in_sizes, int n_in,
                              void* d_out, int out_size)
{
    (void)in_sizes; (void)n_in; (void)out_size;
    const float* query = (const float*)d_in[0];
    const float* key   = (const float*)d_in[1];
    const float* value = (const float*)d_in[2];
    const int*   mask  = (const int*)  d_in[3];
    const float* Wq    = (const float*)d_in[4];
    const float* Wk    = (const float*)d_in[5];
    const float* Wv    = (const float*)d_in[6];
    const float* Wo    = (const float*)d_in[7];
    float* out = (float*)d_out;

    float *pQ, *pK, *pV, *pCtx;
    cudaGetSymbolAddress((void**)&pQ,   g_Q);
    cudaGetSymbolAddress((void**)&pK,   g_K);
    cudaGetSymbolAddress((void**)&pV,   g_V);
    cudaGetSymbolAddress((void**)&pCtx, g_ctx);

    cudaFuncSetAttribute(gqa_attention,
                         cudaFuncAttributeMaxDynamicSharedMemorySize,
                         AT_SMEM_BYTES);

    const int M = PB * PS;   // 4096
    dim3 blk(256);

    // Projections (TF32 tensor cores, 3xTF32 accuracy)
    gemm_tf32<<<dim3(PD / 128,   M / 128), blk>>>(query, Wq, pQ, M, PD,   PD);
    gemm_tf32<<<dim3(PKVD / 128, M / 128), blk>>>(key,   Wk, pK, M, PKVD, PD);
    gemm_tf32<<<dim3(PKVD / 128, M / 128), blk>>>(value, Wv, pV, M, PKVD, PD);

    // Fused attention
    gqa_attention<<<dim3(PS / 64, PH, PB), blk, AT_SMEM_BYTES>>>(pQ, pK, pV, mask, pCtx);

    // Output projection
    gemm_tf32<<<dim3(PD / 128, M / 128), blk>>>(pCtx, Wo, out, M, PD, PD);
}

// round 7
// speedup vs baseline: 1.3549x; 1.2785x over previous
#include <cuda_runtime.h>
#include <cuda_bf16.h>
#include <cstdint>

// Problem constants
#define PB   2
#define PS   2048
#define PD   2048
#define PH   16
#define PHKV 4
#define PDH  128
#define PKVD (PHKV * PDH)   // 512
#define PM   (PB * PS)      // 4096
#define NCH  (PD / 16)      // 128 k16-chunks (K is always 2048)

// ---------------------------------------------------------------------------
// Scratch (device globals: no allocations allowed)
// ---------------------------------------------------------------------------
__device__ float g_Q[(size_t)PM * PD];
__device__ float g_K[(size_t)PM * PKVD];
__device__ float g_V[(size_t)PM * PKVD];
__device__ float g_ctx[(size_t)PM * PD];

// Packed bf16 planes, mma-fragment order.
// A plane: per (row-tile R of 128, chunk c of k16): 8 mtiles x 32 lanes x 4 regs
//          = 4096 B, contiguous at ((R*128 + c) * 4096).
// B plane: per (col-tile NT of 128, chunk c): 16 ntiles x 32 lanes x 2 regs
//          = 4096 B, contiguous at ((NT*128 + c) * 4096).
#define A_PLANE_ELEMS  ((size_t)PM * PD)
#define WQ_PLANE_ELEMS ((size_t)PD * PD)
#define WK_PLANE_ELEMS ((size_t)PD * PKVD)
__device__ __align__(128) __nv_bfloat16 g_aq_h[A_PLANE_ELEMS],  g_aq_l[A_PLANE_ELEMS];
__device__ __align__(128) __nv_bfloat16 g_ak_h[A_PLANE_ELEMS],  g_ak_l[A_PLANE_ELEMS];
__device__ __align__(128) __nv_bfloat16 g_av_h[A_PLANE_ELEMS],  g_av_l[A_PLANE_ELEMS];
__device__ __align__(128) __nv_bfloat16 g_ac_h[A_PLANE_ELEMS],  g_ac_l[A_PLANE_ELEMS];
__device__ __align__(128) __nv_bfloat16 g_wq_h[WQ_PLANE_ELEMS], g_wq_l[WQ_PLANE_ELEMS];
__device__ __align__(128) __nv_bfloat16 g_wo_h[WQ_PLANE_ELEMS], g_wo_l[WQ_PLANE_ELEMS];
__device__ __align__(128) __nv_bfloat16 g_wk_h[WK_PLANE_ELEMS], g_wk_l[WK_PLANE_ELEMS];
__device__ __align__(128) __nv_bfloat16 g_wv_h[WK_PLANE_ELEMS], g_wv_l[WK_PLANE_ELEMS];

// ---------------------------------------------------------------------------
// Helpers
// ---------------------------------------------------------------------------
__device__ __forceinline__ uint32_t smem_u32(const void* p) {
    uint32_t a;
    asm("{ .reg .u64 t; cvta.to.shared.u64 t, %1; cvt.u32.u64 %0, t; }"
        : "=r"(a) : "l"(p));
    return a;
}

__device__ __forceinline__ void cp16(uint32_t dst, const void* src) {
    asm volatile("cp.async.cg.shared.global [%0], [%1], 16;"
                 :: "r"(dst), "l"(src) : "memory");
}

__device__ __forceinline__ void mma_bf16(float* c, const uint32_t* a, const uint32_t* b) {
    asm volatile(
        "mma.sync.aligned.m16n8k16.row.col.f32.bf16.bf16.f32 "
        "{%0,%1,%2,%3}, {%4,%5,%6,%7}, {%8,%9}, {%0,%1,%2,%3};"
        : "+f"(c[0]), "+f"(c[1]), "+f"(c[2]), "+f"(c[3])
        : "r"(a[0]), "r"(a[1]), "r"(a[2]), "r"(a[3]),
          "r"(b[0]), "r"(b[1]));
}

// pack two fp32 -> bf16x2 (lo = first), plus residual pair
__device__ __forceinline__ void split2(float f0, float f1, uint32_t& uh, uint32_t& ul) {
    asm("cvt.rn.bf16x2.f32 %0, %1, %2;" : "=r"(uh) : "f"(f1), "f"(f0));
    float h0 = __uint_as_float(uh << 16);
    float h1 = __uint_as_float(uh & 0xFFFF0000u);
    float l0 = f0 - h0, l1 = f1 - h1;
    asm("cvt.rn.bf16x2.f32 %0, %1, %2;" : "=r"(ul) : "f"(l1), "f"(l0));
}

// ---------------------------------------------------------------------------
// pack_a: A [M=4096, K=2048] fp32 row-major -> hi/lo planes in A-fragment order.
// Fragment (m16n8k16 row-major A): lane = g*4+t4; regs j = (row>=8) + 2*(k>=8).
// ---------------------------------------------------------------------------
__global__ void pack_a(const float* __restrict__ src,
                       __nv_bfloat16* __restrict__ hi,
                       __nv_bfloat16* __restrict__ lo)
{
    int idx = blockIdx.x * 256 + threadIdx.x;   // over M*K/2
    int m  = idx >> 10;                         // K/2 = 1024 float2 per row
    int k  = (idx & 1023) * 2;
    float2 f = ((const float2*)src)[idx];
    uint32_t uh, ul;
    split2(f.x, f.y, uh, ul);

    int R = m >> 7, rr = m & 127;
    int mtile = rr >> 4, r16 = rr & 15;
    int g = r16 & 7, hi8 = r16 >> 3;
    int c = k >> 4, kk = k & 15;
    int t4 = (kk >> 1) & 3, khi = kk >> 3;
    int lane = g * 4 + t4;
    int j = hi8 + 2 * khi;
    size_t off = (((size_t)R * NCH + c) * 8 + mtile) * 512 + lane * 16 + j * 4;
    *(uint32_t*)((char*)hi + off) = uh;
    *(uint32_t*)((char*)lo + off) = ul;
}

// ---------------------------------------------------------------------------
// pack_wT: W [K=2048, N] fp32 row-major -> hi/lo planes in B-fragment order
// (col-major n8k16 of B). grid (N/32, K/32), block (32, 8).
// ---------------------------------------------------------------------------
__global__ void pack_wT(const float* __restrict__ w,
                        __nv_bfloat16* __restrict__ hi,
                        __nv_bfloat16* __restrict__ lo, int N)
{
    __shared__ float t[32][33];
    const int tx = threadIdx.x, ty = threadIdx.y;
    const int nx = blockIdx.x * 32, k0 = blockIdx.y * 32;

    #pragma unroll
    for (int j = 0; j < 32; j += 8)
        t[ty + j][tx] = w[(size_t)(k0 + ty + j) * N + nx + tx];
    __syncthreads();

    if (tx < 16) {
        const int k  = k0 + 2 * tx;
        const int c  = k >> 4, kk = k & 15;
        const int t4 = (kk >> 1) & 3, khi = kk >> 3;
        #pragma unroll
        for (int j = 0; j < 32; j += 8) {
            const int n = nx + ty + j;
            uint32_t uh, ul;
            split2(t[2 * tx][ty + j], t[2 * tx + 1][ty + j], uh, ul);
            const int NT = n >> 7, nn = n & 127;
            const int ntile = nn >> 3, g = nn & 7;
            const int lane = g * 4 + t4;
            size_t off = (((size_t)NT * NCH + c) * 16 + ntile) * 256 + lane * 8 + khi * 4;
            *(uint32_t*)((char*)hi + off) = uh;
            *(uint32_t*)((char*)lo + off) = ul;
        }
    }
}

// ---------------------------------------------------------------------------
// bf16 mma GEMM, 3-term split: C = A @ B^T over K=2048.
// Block 128x128, 256 threads (8 warps, 2x4), warp tile 64x32.
// 6-stage cp.async pipeline, 16KB/stage: [Ah|Al|Bh|Bl] x 4KB, fragment order.
// ---------------------------------------------------------------------------
#define NSTG       6
#define STG_BYTES  16384
#define GEMM_SMEM  (NSTG * STG_BYTES)   // 98304

__global__ __launch_bounds__(256, 1)
void tc_gemm(const __nv_bfloat16* __restrict__ Ah, const __nv_bfloat16* __restrict__ Al,
             const __nv_bfloat16* __restrict__ Bh, const __nv_bfloat16* __restrict__ Bl,
             float* __restrict__ C, int N)
{
    extern __shared__ char dsm[];
    const int tid  = threadIdx.x;
    const int lane = tid & 31;
    const int wid  = tid >> 5;
    const int warp_m = wid >> 2;    // 0..1
    const int warp_n = wid & 3;     // 0..3
    const int mt0 = blockIdx.y, nt0 = blockIdx.x;

    const char* pAh = (const char*)Ah + (size_t)mt0 * NCH * 4096;
    const char* pAl = (const char*)Al + (size_t)mt0 * NCH * 4096;
    const char* pBh = (const char*)Bh + (size_t)nt0 * NCH * 4096;
    const char* pBl = (const char*)Bl + (size_t)nt0 * NCH * 4096;

    const uint32_t sbase = smem_u32(dsm);
    const int t16 = tid * 16;

    // Prologue: fill NSTG-1 stages
    #pragma unroll
    for (int s = 0; s < NSTG - 1; s++) {
        const uint32_t d = sbase + s * STG_BYTES + t16;
        const size_t o = (size_t)s * 4096 + t16;
        cp16(d,         pAh + o);
        cp16(d + 4096,  pAl + o);
        cp16(d + 8192,  pBh + o);
        cp16(d + 12288, pBl + o);
        asm volatile("cp.async.commit_group;" ::: "memory");
    }

    float acc[4][4][4];
    #pragma unroll
    for (int mt = 0; mt < 4; mt++)
        #pragma unroll
        for (int nt = 0; nt < 4; nt++)
            #pragma unroll
            for (int j = 0; j < 4; j++) acc[mt][nt][j] = 0.0f;

    for (int c = 0; c < NCH; c++) {
        asm volatile("cp.async.wait_group %0;" :: "n"(NSTG - 2) : "memory");
        __syncthreads();

        const int nc = c + NSTG - 1;
        if (nc < NCH) {
            const uint32_t d = sbase + (nc % NSTG) * STG_BYTES + t16;
            const size_t o = (size_t)nc * 4096 + t16;
            cp16(d,         pAh + o);
            cp16(d + 4096,  pAl + o);
            cp16(d + 8192,  pBh + o);
            cp16(d + 12288, pBl + o);
        }
        asm volatile("cp.async.commit_group;" ::: "memory");

        const char* stg = dsm + (c % NSTG) * STG_BYTES;
        const uint4* sAh = (const uint4*)(stg);
        const uint4* sAl = (const uint4*)(stg + 4096);
        const uint2* sBh = (const uint2*)(stg + 8192);
        const uint2* sBl = (const uint2*)(stg + 12288);

        uint32_t ahi[4][4], alo[4][4], bhi[4][2], blo[4][2];
        #pragma unroll
        for (int mt = 0; mt < 4; mt++) {
            uint4 h = sAh[(warp_m * 4 + mt) * 32 + lane];
            ahi[mt][0] = h.x; ahi[mt][1] = h.y; ahi[mt][2] = h.z; ahi[mt][3] = h.w;
            uint4 l = sAl[(warp_m * 4 + mt) * 32 + lane];
            alo[mt][0] = l.x; alo[mt][1] = l.y; alo[mt][2] = l.z; alo[mt][3] = l.w;
        }
        #pragma unroll
        for (int nt = 0; nt < 4; nt++) {
            uint2 h = sBh[(warp_n * 4 + nt) * 32 + lane];
            bhi[nt][0] = h.x; bhi[nt][1] = h.y;
            uint2 l = sBl[(warp_n * 4 + nt) * 32 + lane];
            blo[nt][0] = l.x; blo[nt][1] = l.y;
        }

        // Term-major ordering: same-acc reuse distance = 16 mma
        #pragma unroll
        for (int mt = 0; mt < 4; mt++)
            #pragma unroll
            for (int nt = 0; nt < 4; nt++)
                mma_bf16(acc[mt][nt], ahi[mt], bhi[nt]);
        #pragma unroll
        for (int mt = 0; mt < 4; mt++)
            #pragma unroll
            for (int nt = 0; nt < 4; nt++)
                mma_bf16(acc[mt][nt], ahi[mt], blo[nt]);
        #pragma unroll
        for (int mt = 0; mt < 4; mt++)
            #pragma unroll
            for (int nt = 0; nt < 4; nt++)
                mma_bf16(acc[mt][nt], alo[mt], bhi[nt]);
    }

    // Epilogue: c0=(g,2t4) c1=(g,2t4+1) c2=(g+8,2t4) c3=(g+8,2t4+1)
    const int g  = lane >> 2;
    const int t4 = lane & 3;
    #pragma unroll
    for (int mt = 0; mt < 4; mt++) {
        #pragma unroll
        for (int nt = 0; nt < 4; nt++) {
            const int row = mt0 * 128 + warp_m * 64 + mt * 16 + g;
            const int col = nt0 * 128 + warp_n * 32 + nt * 8 + 2 * t4;
            float* Cp = C + (size_t)row * N + col;
            *(float2*)(Cp)                 = make_float2(acc[mt][nt][0], acc[mt][nt][1]);
            *(float2*)(Cp + (size_t)8 * N) = make_float2(acc[mt][nt][2], acc[mt][nt][3]);
        }
    }
}

// ---------------------------------------------------------------------------
// Fused GQA flash attention. smem 115712B -> 2 CTAs/SM.
// ---------------------------------------------------------------------------
#define AT_SMEM_FLOATS (128*64 + 128*64 + 64*128 + 64*68)   // 28928
#define AT_SMEM_BYTES  (AT_SMEM_FLOATS * 4)                 // 115712

__global__ __launch_bounds__(256, 2)
void gqa_attention(const float* __restrict__ Q, const float* __restrict__ Kp,
                   const float* __restrict__ Vp, const int* __restrict__ mask,
                   float* __restrict__ ctx)
{
    extern __shared__ float smem[];
    float* sQT = smem;                   // [128][64]  d-major
    float* sKT = sQT + 128 * 64;         // [128][64]  d-major
    float* sV  = sKT + 128 * 64;         // [64][128]  row-major
    float* sP  = sV  + 64 * 128;         // [64][68]   padded

    const int tid = threadIdx.x;
    const int tx  = tid & 15;
    const int ty  = tid >> 4;
    const int q0  = blockIdx.x * 64;
    const int h   = blockIdx.y;
    const int b   = blockIdx.z;
    const int g   = h >> 2;

    const float scale = 0.08838834764831845f;   // 1/sqrt(128)

    {
        const int r  = tid & 63;
        const int cb = (tid >> 6) * 32;
        const float* gq = Q + ((size_t)(b * PS + q0 + r)) * PD + h * PDH + cb;
        #pragma unroll
        for (int i = 0; i < 8; i++) {
            float4 v = *(const float4*)(gq + 4 * i);
            const int c = cb + 4 * i;
            sQT[(c + 0) * 64 + r] = v.x;
            sQT[(c + 1) * 64 + r] = v.y;
            sQT[(c + 2) * 64 + r] = v.z;
            sQT[(c + 3) * 64 + r] = v.w;
        }
    }

    float o[4][8];
    #pragma unroll
    for (int i = 0; i < 4; i++)
        #pragma unroll
        for (int j = 0; j < 8; j++) o[i][j] = 0.0f;
    float mrow[4], lrow[4];
    #pragma unroll
    for (int i = 0; i < 4; i++) { mrow[i] = -3.0e38f; lrow[i] = 0.0f; }

    for (int kt = 0; kt < PS / 64; kt++) {
        const int k0 = kt * 64;
        __syncthreads();

        {
            const int r  = tid & 63;
            const int cb = (tid >> 6) * 32;
            const float* gk = Kp + ((size_t)(b * PS + k0 + r)) * PKVD + g * PDH + cb;
            #pragma unroll
            for (int i = 0; i < 8; i++) {
                float4 v = *(const float4*)(gk + 4 * i);
                const int c = cb + 4 * i;
                sKT[(c + 0) * 64 + r] = v.x;
                sKT[(c + 1) * 64 + r] = v.y;
                sKT[(c + 2) * 64 + r] = v.z;
                sKT[(c + 3) * 64 + r] = v.w;
            }
            const int vr  = tid >> 2;
            const int vcb = (tid & 3) * 32;
            const float* gv = Vp + ((size_t)(b * PS + k0 + vr)) * PKVD + g * PDH + vcb;
            float* dv = sV + vr * 128 + vcb;
            #pragma unroll
            for (int i = 0; i < 8; i++)
                *(float4*)(dv + 4 * i) = *(const float4*)(gv + 4 * i);
        }
        __syncthreads();

        float acc[4][4];
        #pragma unroll
        for (int i = 0; i < 4; i++)
            #pragma unroll
            for (int j = 0; j < 4; j++) acc[i][j] = 0.0f;

        #pragma unroll 8
        for (int d = 0; d < 128; d++) {
            const float4 q4 = *(const float4*)(sQT + d * 64 + (ty << 2));
            const float4 k4 = *(const float4*)(sKT + d * 64 + (tx << 2));
            const float qv[4] = {q4.x, q4.y, q4.z, q4.w};
            const float kv[4] = {k4.x, k4.y, k4.z, k4.w};
            #pragma unroll
            for (int i = 0; i < 4; i++)
                #pragma unroll
                for (int j = 0; j < 4; j++)
                    acc[i][j] = fmaf(qv[i], kv[j], acc[i][j]);
        }

        #pragma unroll
        for (int i = 0; i < 4; i++) {
            const int4 mv = *(const int4*)(mask +
                ((size_t)(b * PS + q0 + ty * 4 + i)) * PS + k0 + tx * 4);
            float s0 = mv.x ? acc[i][0] * scale : -1e9f;
            float s1 = mv.y ? acc[i][1] * scale : -1e9f;
            float s2 = mv.z ? acc[i][2] * scale : -1e9f;
            float s3 = mv.w ? acc[i][3] * scale : -1e9f;

            float tmax = fmaxf(fmaxf(s0, s1), fmaxf(s2, s3));
            #pragma unroll
            for (int off = 8; off > 0; off >>= 1)
                tmax = fmaxf(tmax, __shfl_xor_sync(0xffffffffu, tmax, off, 16));

            const float mnew  = fmaxf(mrow[i], tmax);
            const float alpha = __expf(mrow[i] - mnew);
            const float p0 = __expf(s0 - mnew);
            const float p1 = __expf(s1 - mnew);
            const float p2 = __expf(s2 - mnew);
            const float p3 = __expf(s3 - mnew);
            float rs = p0 + p1 + p2 + p3;
            #pragma unroll
            for (int off = 8; off > 0; off >>= 1)
                rs += __shfl_xor_sync(0xffffffffu, rs, off, 16);

            lrow[i] = lrow[i] * alpha + rs;
            mrow[i] = mnew;
            *(float4*)(sP + (ty * 4 + i) * 68 + tx * 4) = make_float4(p0, p1, p2, p3);
            #pragma unroll
            for (int j = 0; j < 8; j++) o[i][j] *= alpha;
        }
        __syncthreads();

        #pragma unroll 4
        for (int k = 0; k < 64; k++) {
            const float4 va = *(const float4*)(sV + k * 128 + (tx << 3));
            const float4 vb = *(const float4*)(sV + k * 128 + (tx << 3) + 4);
            const float vv[8] = {va.x, va.y, va.z, va.w, vb.x, vb.y, vb.z, vb.w};
            #pragma unroll
            for (int i = 0; i < 4; i++) {
                const float p = sP[(ty * 4 + i) * 68 + k];
                #pragma unroll
                for (int j = 0; j < 8; j++)
                    o[i][j] = fmaf(p, vv[j], o[i][j]);
            }
        }
    }

    #pragma unroll
    for (int i = 0; i < 4; i++) {
        const float inv = 1.0f / lrow[i];
        float* cp = ctx + ((size_t)(b * PS + q0 + ty * 4 + i)) * PD + h * PDH + tx * 8;
        *(float4*)(cp)     = make_float4(o[i][0] * inv, o[i][1] * inv,
                                         o[i][2] * inv, o[i][3] * inv);
        *(float4*)(cp + 4) = make_float4(o[i][4] * inv, o[i][5] * inv,
                                         o[i][6] * inv, o[i][7] * inv);
    }
}

// ---------------------------------------------------------------------------
// Launch
// ---------------------------------------------------------------------------
extern "C" void kernel_launch(void* const* d_in, const int* in_sizes, int n_in,
                              void* d_out, int out_size)
{
    (void)in_sizes; (void)n_in; (void)out_size;
    const float* query = (const float*)d_in[0];
    const float* key   = (const float*)d_in[1];
    const float* value = (const float*)d_in[2];
    const int*   mask  = (const int*)  d_in[3];
    const float* Wq    = (const float*)d_in[4];
    const float* Wk    = (const float*)d_in[5];
    const float* Wv    = (const float*)d_in[6];
    const float* Wo    = (const float*)d_in[7];
    float* out = (float*)d_out;

    float *pQ, *pK, *pV, *pCtx;
    cudaGetSymbolAddress((void**)&pQ,   g_Q);
    cudaGetSymbolAddress((void**)&pK,   g_K);
    cudaGetSymbolAddress((void**)&pV,   g_V);
    cudaGetSymbolAddress((void**)&pCtx, g_ctx);

    __nv_bfloat16 *aq_h, *aq_l, *ak_h, *ak_l, *av_h, *av_l, *ac_h, *ac_l;
    __nv_bfloat16 *wq_h, *wq_l, *wk_h, *wk_l, *wv_h, *wv_l, *wo_h, *wo_l;
    cudaGetSymbolAddress((void**)&aq_h, g_aq_h); cudaGetSymbolAddress((void**)&aq_l, g_aq_l);
    cudaGetSymbolAddress((void**)&ak_h, g_ak_h); cudaGetSymbolAddress((void**)&ak_l, g_ak_l);
    cudaGetSymbolAddress((void**)&av_h, g_av_h); cudaGetSymbolAddress((void**)&av_l, g_av_l);
    cudaGetSymbolAddress((void**)&ac_h, g_ac_h); cudaGetSymbolAddress((void**)&ac_l, g_ac_l);
    cudaGetSymbolAddress((void**)&wq_h, g_wq_h); cudaGetSymbolAddress((void**)&wq_l, g_wq_l);
    cudaGetSymbolAddress((void**)&wk_h, g_wk_h); cudaGetSymbolAddress((void**)&wk_l, g_wk_l);
    cudaGetSymbolAddress((void**)&wv_h, g_wv_h); cudaGetSymbolAddress((void**)&wv_l, g_wv_l);
    cudaGetSymbolAddress((void**)&wo_h, g_wo_h); cudaGetSymbolAddress((void**)&wo_l, g_wo_l);

    cudaFuncSetAttribute(tc_gemm, cudaFuncAttributeMaxDynamicSharedMemorySize, GEMM_SMEM);
    cudaFuncSetAttribute(gqa_attention, cudaFuncAttributeMaxDynamicSharedMemorySize,
                         AT_SMEM_BYTES);

    const int PACK_A_BLOCKS = (PM * PD / 2) / 256;   // 16384

    // Pack weights (transpose + split into B-fragment order)
    pack_wT<<<dim3(PD / 32, PD / 32),   dim3(32, 8)>>>(Wq, wq_h, wq_l, PD);
    pack_wT<<<dim3(PKVD / 32, PD / 32), dim3(32, 8)>>>(Wk, wk_h, wk_l, PKVD);
    pack_wT<<<dim3(PKVD / 32, PD / 32), dim3(32, 8)>>>(Wv, wv_h, wv_l, PKVD);
    pack_wT<<<dim3(PD / 32, PD / 32),   dim3(32, 8)>>>(Wo, wo_h, wo_l, PD);

    // Pack activations (split into A-fragment order)
    pack_a<<<PACK_A_BLOCKS, 256>>>(query, aq_h, aq_l);
    pack_a<<<PACK_A_BLOCKS, 256>>>(key,   ak_h, ak_l);
    pack_a<<<PACK_A_BLOCKS, 256>>>(value, av_h, av_l);

    // Projections (bf16 mma, 3-term split)
    tc_gemm<<<dim3(PD / 128,   PM / 128), 256, GEMM_SMEM>>>(aq_h, aq_l, wq_h, wq_l, pQ, PD);
    tc_gemm<<<dim3(PKVD / 128, PM / 128), 256, GEMM_SMEM>>>(ak_h, ak_l, wk_h, wk_l, pK, PKVD);
    tc_gemm<<<dim3(PKVD / 128, PM / 128), 256, GEMM_SMEM>>>(av_h, av_l, wv_h, wv_l, pV, PKVD);

    // Fused attention
    gqa_attention<<<dim3(PS / 64, PH, PB), 256, AT_SMEM_BYTES>>>(pQ, pK, pV, mask, pCtx);

    // Output projection
    pack_a<<<PACK_A_BLOCKS, 256>>>(pCtx, ac_h, ac_l);
    tc_gemm<<<dim3(PD / 128, PM / 128), 256, GEMM_SMEM>>>(ac_h, ac_l, wo_h, wo_l, out, PD);
}

// round 8
// speedup vs baseline: 3.2620x; 2.4075x over previous
#include <cuda_runtime.h>
#include <cuda_bf16.h>
#include <cstdint>

// Problem constants
#define PB   2
#define PS   2048
#define PD   2048
#define PH   16
#define PHKV 4
#define PDH  128
#define PKVD (PHKV * PDH)   // 512
#define PM   (PB * PS)      // 4096
#define NCH  (PD / 16)      // 128 k16-chunks for GEMM

// ---------------------------------------------------------------------------
// Scratch (device globals: no allocations allowed)
// ---------------------------------------------------------------------------
__device__ float g_Q[(size_t)PM * PD];
__device__ float g_K[(size_t)PM * PKVD];
__device__ float g_V[(size_t)PM * PKVD];
__device__ float g_ctx[(size_t)PM * PD];

// GEMM packed planes (fragment order) — validated R7
#define A_PLANE_ELEMS  ((size_t)PM * PD)
#define WQ_PLANE_ELEMS ((size_t)PD * PD)
#define WK_PLANE_ELEMS ((size_t)PD * PKVD)
__device__ __align__(128) __nv_bfloat16 g_aq_h[A_PLANE_ELEMS],  g_aq_l[A_PLANE_ELEMS];
__device__ __align__(128) __nv_bfloat16 g_ak_h[A_PLANE_ELEMS],  g_ak_l[A_PLANE_ELEMS];
__device__ __align__(128) __nv_bfloat16 g_av_h[A_PLANE_ELEMS],  g_av_l[A_PLANE_ELEMS];
__device__ __align__(128) __nv_bfloat16 g_ac_h[A_PLANE_ELEMS],  g_ac_l[A_PLANE_ELEMS];
__device__ __align__(128) __nv_bfloat16 g_wq_h[WQ_PLANE_ELEMS], g_wq_l[WQ_PLANE_ELEMS];
__device__ __align__(128) __nv_bfloat16 g_wo_h[WQ_PLANE_ELEMS], g_wo_l[WQ_PLANE_ELEMS];
__device__ __align__(128) __nv_bfloat16 g_wk_h[WK_PLANE_ELEMS], g_wk_l[WK_PLANE_ELEMS];
__device__ __align__(128) __nv_bfloat16 g_wv_h[WK_PLANE_ELEMS], g_wv_l[WK_PLANE_ELEMS];

// Attention packed planes (fragment order)
__device__ __align__(128) __nv_bfloat16 g_qa_h[(size_t)PM * PD],   g_qa_l[(size_t)PM * PD];
__device__ __align__(128) __nv_bfloat16 g_kb_h[(size_t)PM * PKVD], g_kb_l[(size_t)PM * PKVD];
__device__ __align__(128) __nv_bfloat16 g_vb_h[(size_t)PM * PKVD], g_vb_l[(size_t)PM * PKVD];

// ---------------------------------------------------------------------------
// Helpers
// ---------------------------------------------------------------------------
__device__ __forceinline__ uint32_t smem_u32(const void* p) {
    uint32_t a;
    asm("{ .reg .u64 t; cvta.to.shared.u64 t, %1; cvt.u32.u64 %0, t; }"
        : "=r"(a) : "l"(p));
    return a;
}

__device__ __forceinline__ void cp16(uint32_t dst, const void* src) {
    asm volatile("cp.async.cg.shared.global [%0], [%1], 16;"
                 :: "r"(dst), "l"(src) : "memory");
}

__device__ __forceinline__ void mma_bf16(float* c, const uint32_t* a, const uint32_t* b) {
    asm volatile(
        "mma.sync.aligned.m16n8k16.row.col.f32.bf16.bf16.f32 "
        "{%0,%1,%2,%3}, {%4,%5,%6,%7}, {%8,%9}, {%0,%1,%2,%3};"
        : "+f"(c[0]), "+f"(c[1]), "+f"(c[2]), "+f"(c[3])
        : "r"(a[0]), "r"(a[1]), "r"(a[2]), "r"(a[3]),
          "r"(b[0]), "r"(b[1]));
}

// pack two fp32 -> bf16x2 (f0 in low half) + residual pair
__device__ __forceinline__ void split2(float f0, float f1, uint32_t& uh, uint32_t& ul) {
    asm("cvt.rn.bf16x2.f32 %0, %1, %2;" : "=r"(uh) : "f"(f1), "f"(f0));
    float h0 = __uint_as_float(uh << 16);
    float h1 = __uint_as_float(uh & 0xFFFF0000u);
    float l0 = f0 - h0, l1 = f1 - h1;
    asm("cvt.rn.bf16x2.f32 %0, %1, %2;" : "=r"(ul) : "f"(l1), "f"(l0));
}

// ---------------------------------------------------------------------------
// GEMM pack kernels (validated R7)
// ---------------------------------------------------------------------------
__global__ void pack_a(const float* __restrict__ src,
                       __nv_bfloat16* __restrict__ hi,
                       __nv_bfloat16* __restrict__ lo)
{
    int idx = blockIdx.x * 256 + threadIdx.x;
    int m  = idx >> 10;
    int k  = (idx & 1023) * 2;
    float2 f = ((const float2*)src)[idx];
    uint32_t uh, ul;
    split2(f.x, f.y, uh, ul);

    int R = m >> 7, rr = m & 127;
    int mtile = rr >> 4, r16 = rr & 15;
    int g = r16 & 7, hi8 = r16 >> 3;
    int c = k >> 4, kk = k & 15;
    int t4 = (kk >> 1) & 3, khi = kk >> 3;
    int lane = g * 4 + t4;
    int j = hi8 + 2 * khi;
    size_t off = (((size_t)R * NCH + c) * 8 + mtile) * 512 + lane * 16 + j * 4;
    *(uint32_t*)((char*)hi + off) = uh;
    *(uint32_t*)((char*)lo + off) = ul;
}

__global__ void pack_wT(const float* __restrict__ w,
                        __nv_bfloat16* __restrict__ hi,
                        __nv_bfloat16* __restrict__ lo, int N)
{
    __shared__ float t[32][33];
    const int tx = threadIdx.x, ty = threadIdx.y;
    const int nx = blockIdx.x * 32, k0 = blockIdx.y * 32;

    #pragma unroll
    for (int j = 0; j < 32; j += 8)
        t[ty + j][tx] = w[(size_t)(k0 + ty + j) * N + nx + tx];
    __syncthreads();

    if (tx < 16) {
        const int k  = k0 + 2 * tx;
        const int c  = k >> 4, kk = k & 15;
        const int t4 = (kk >> 1) & 3, khi = kk >> 3;
        #pragma unroll
        for (int j = 0; j < 32; j += 8) {
            const int n = nx + ty + j;
            uint32_t uh, ul;
            split2(t[2 * tx][ty + j], t[2 * tx + 1][ty + j], uh, ul);
            const int NT = n >> 7, nn = n & 127;
            const int ntile = nn >> 3, g = nn & 7;
            const int lane = g * 4 + t4;
            size_t off = (((size_t)NT * NCH + c) * 16 + ntile) * 256 + lane * 8 + khi * 4;
            *(uint32_t*)((char*)hi + off) = uh;
            *(uint32_t*)((char*)lo + off) = ul;
        }
    }
}

// ---------------------------------------------------------------------------
// Attention pack kernels
// ---------------------------------------------------------------------------
// Q -> A-fragment planes, scale folded in.
// plane offset: ((((b*PH+h)*16+qt)*8+w)*8 + k16)*512 + lane*16 + reg*4 (+parity*2)
__global__ void pack_qa(const float* __restrict__ src,
                        __nv_bfloat16* __restrict__ hi,
                        __nv_bfloat16* __restrict__ lo)
{
    const float scale = 0.08838834764831845f;   // 1/sqrt(128)
    int idx = blockIdx.x * 256 + threadIdx.x;   // over PM*PD/2
    int m  = idx >> 10;
    int dg = (idx & 1023) * 2;
    float2 f = ((const float2*)src)[idx];
    uint32_t uh, ul;
    split2(f.x * scale, f.y * scale, uh, ul);

    int b = m >> 11, s = m & 2047;
    int h = dg >> 7, d = dg & 127;
    int qt = s >> 7, rr = s & 127;
    int w = rr >> 4, r16 = rr & 15;
    int g = r16 & 7, hi8 = r16 >> 3;
    int k16 = d >> 4, dd = d & 15;
    int t4 = (dd >> 1) & 3, khi = dd >> 3;
    size_t off = (((((size_t)(b * PH + h) * 16 + qt) * 8 + w) * 8 + k16) * 512)
               + (g * 4 + t4) * 16 + (hi8 + 2 * khi) * 4;
    *(uint32_t*)((char*)hi + off) = uh;
    *(uint32_t*)((char*)lo + off) = ul;
}

// K -> B-fragment planes for S-mma (n = kseq, k = dh).
// plane offset: (((b*4+g)*32+kt)*64 + n8*8 + k16)*256 + lane*8 + khi*4
__global__ void pack_kb(const float* __restrict__ src,
                        __nv_bfloat16* __restrict__ hi,
                        __nv_bfloat16* __restrict__ lo)
{
    int idx = blockIdx.x * 256 + threadIdx.x;   // over PM*PKVD/2
    int m  = idx >> 8;
    int dg = (idx & 255) * 2;
    float2 f = ((const float2*)src)[idx];
    uint32_t uh, ul;
    split2(f.x, f.y, uh, ul);

    int b = m >> 11, s = m & 2047;
    int gkv = dg >> 7, d = dg & 127;
    int kt = s >> 6, sk = s & 63;
    int n8 = sk >> 3, gN = sk & 7;
    int k16 = d >> 4, dd = d & 15;
    int t4 = (dd >> 1) & 3, khi = dd >> 3;
    size_t off = ((((size_t)(b * PHKV + gkv) * 32 + kt) * 64) + n8 * 8 + k16) * 256
               + (gN * 4 + t4) * 8 + khi * 4;
    *(uint32_t*)((char*)hi + off) = uh;
    *(uint32_t*)((char*)lo + off) = ul;
}

// V -> B-fragment planes for PV-mma (n = dh, k = kseq).
// plane offset: (((b*4+g)*32+kt)*64 + n8*4 + k16)*256 + lane*8 + khi*4
__global__ void pack_vb(const float* __restrict__ src,
                        __nv_bfloat16* __restrict__ hi,
                        __nv_bfloat16* __restrict__ lo)
{
    int idx = blockIdx.x * 256 + threadIdx.x;   // over (PM/2)*PKVD
    int rp = idx >> 9;
    int dg = idx & 511;
    int s0 = rp * 2;
    float f0 = src[(size_t)s0 * PKVD + dg];
    float f1 = src[(size_t)(s0 + 1) * PKVD + dg];
    uint32_t uh, ul;
    split2(f0, f1, uh, ul);

    int b = s0 >> 11, s = s0 & 2047;
    int gkv = dg >> 7, d = dg & 127;
    int kt = s >> 6, sk = s & 63;
    int k16 = sk >> 4, kk = sk & 15;
    int t4 = (kk >> 1) & 3, khi = kk >> 3;
    int n8 = d >> 3, gN = d & 7;
    size_t off = ((((size_t)(b * PHKV + gkv) * 32 + kt) * 64) + n8 * 4 + k16) * 256
               + (gN * 4 + t4) * 8 + khi * 4;
    *(uint32_t*)((char*)hi + off) = uh;
    *(uint32_t*)((char*)lo + off) = ul;
}

// ---------------------------------------------------------------------------
// bf16 mma GEMM, 3-term split (validated R7)
// ---------------------------------------------------------------------------
#define NSTG       6
#define STG_BYTES  16384
#define GEMM_SMEM  (NSTG * STG_BYTES)

__global__ __launch_bounds__(256, 1)
void tc_gemm(const __nv_bfloat16* __restrict__ Ah, const __nv_bfloat16* __restrict__ Al,
             const __nv_bfloat16* __restrict__ Bh, const __nv_bfloat16* __restrict__ Bl,
             float* __restrict__ C, int N)
{
    extern __shared__ char dsm[];
    const int tid  = threadIdx.x;
    const int lane = tid & 31;
    const int wid  = tid >> 5;
    const int warp_m = wid >> 2;
    const int warp_n = wid & 3;
    const int mt0 = blockIdx.y, nt0 = blockIdx.x;

    const char* pAh = (const char*)Ah + (size_t)mt0 * NCH * 4096;
    const char* pAl = (const char*)Al + (size_t)mt0 * NCH * 4096;
    const char* pBh = (const char*)Bh + (size_t)nt0 * NCH * 4096;
    const char* pBl = (const char*)Bl + (size_t)nt0 * NCH * 4096;

    const uint32_t sbase = smem_u32(dsm);
    const int t16 = tid * 16;

    #pragma unroll
    for (int s = 0; s < NSTG - 1; s++) {
        const uint32_t d = sbase + s * STG_BYTES + t16;
        const size_t o = (size_t)s * 4096 + t16;
        cp16(d,         pAh + o);
        cp16(d + 4096,  pAl + o);
        cp16(d + 8192,  pBh + o);
        cp16(d + 12288, pBl + o);
        asm volatile("cp.async.commit_group;" ::: "memory");
    }

    float acc[4][4][4];
    #pragma unroll
    for (int mt = 0; mt < 4; mt++)
        #pragma unroll
        for (int nt = 0; nt < 4; nt++)
            #pragma unroll
            for (int j = 0; j < 4; j++) acc[mt][nt][j] = 0.0f;

    for (int c = 0; c < NCH; c++) {
        asm volatile("cp.async.wait_group %0;" :: "n"(NSTG - 2) : "memory");
        __syncthreads();

        const int nc = c + NSTG - 1;
        if (nc < NCH) {
            const uint32_t d = sbase + (nc % NSTG) * STG_BYTES + t16;
            const size_t o = (size_t)nc * 4096 + t16;
            cp16(d,         pAh + o);
            cp16(d + 4096,  pAl + o);
            cp16(d + 8192,  pBh + o);
            cp16(d + 12288, pBl + o);
        }
        asm volatile("cp.async.commit_group;" ::: "memory");

        const char* stg = dsm + (c % NSTG) * STG_BYTES;
        const uint4* sAh = (const uint4*)(stg);
        const uint4* sAl = (const uint4*)(stg + 4096);
        const uint2* sBh = (const uint2*)(stg + 8192);
        const uint2* sBl = (const uint2*)(stg + 12288);

        uint32_t ahi[4][4], alo[4][4], bhi[4][2], blo[4][2];
        #pragma unroll
        for (int mt = 0; mt < 4; mt++) {
            uint4 h = sAh[(warp_m * 4 + mt) * 32 + lane];
            ahi[mt][0] = h.x; ahi[mt][1] = h.y; ahi[mt][2] = h.z; ahi[mt][3] = h.w;
            uint4 l = sAl[(warp_m * 4 + mt) * 32 + lane];
            alo[mt][0] = l.x; alo[mt][1] = l.y; alo[mt][2] = l.z; alo[mt][3] = l.w;
        }
        #pragma unroll
        for (int nt = 0; nt < 4; nt++) {
            uint2 h = sBh[(warp_n * 4 + nt) * 32 + lane];
            bhi[nt][0] = h.x; bhi[nt][1] = h.y;
            uint2 l = sBl[(warp_n * 4 + nt) * 32 + lane];
            blo[nt][0] = l.x; blo[nt][1] = l.y;
        }

        #pragma unroll
        for (int mt = 0; mt < 4; mt++)
            #pragma unroll
            for (int nt = 0; nt < 4; nt++)
                mma_bf16(acc[mt][nt], ahi[mt], bhi[nt]);
        #pragma unroll
        for (int mt = 0; mt < 4; mt++)
            #pragma unroll
            for (int nt = 0; nt < 4; nt++)
                mma_bf16(acc[mt][nt], ahi[mt], blo[nt]);
        #pragma unroll
        for (int mt = 0; mt < 4; mt++)
            #pragma unroll
            for (int nt = 0; nt < 4; nt++)
                mma_bf16(acc[mt][nt], alo[mt], bhi[nt]);
    }

    const int g  = lane >> 2;
    const int t4 = lane & 3;
    #pragma unroll
    for (int mt = 0; mt < 4; mt++) {
        #pragma unroll
        for (int nt = 0; nt < 4; nt++) {
            const int row = mt0 * 128 + warp_m * 64 + mt * 16 + g;
            const int col = nt0 * 128 + warp_n * 32 + nt * 8 + 2 * t4;
            float* Cp = C + (size_t)row * N + col;
            *(float2*)(Cp)                 = make_float2(acc[mt][nt][0], acc[mt][nt][1]);
            *(float2*)(Cp + (size_t)8 * N) = make_float2(acc[mt][nt][2], acc[mt][nt][3]);
        }
    }
}

// ---------------------------------------------------------------------------
// Tensor-core fused GQA flash attention.
// Grid (S/128, H, B), 256 threads (8 warps x 16 q-rows). BK=64.
// smem: 2 stages x [Kh 16K | Kl 16K | Vh 16K | Vl 16K] = 128KB.
// ---------------------------------------------------------------------------
#define ATT_STG    65536
#define ATT_SMEM   (2 * ATT_STG)

__global__ __launch_bounds__(256, 1)
void gqa_attn_mma(const __nv_bfloat16* __restrict__ Qh, const __nv_bfloat16* __restrict__ Ql,
                  const __nv_bfloat16* __restrict__ Kh, const __nv_bfloat16* __restrict__ Kl,
                  const __nv_bfloat16* __restrict__ Vh, const __nv_bfloat16* __restrict__ Vl,
                  const int* __restrict__ mask, float* __restrict__ ctx)
{
    extern __shared__ char dsm[];
    const int tid  = threadIdx.x;
    const int lane = tid & 31;
    const int w    = tid >> 5;
    const int g    = lane >> 2;
    const int t4   = lane & 3;
    const int qt   = blockIdx.x;
    const int h    = blockIdx.y;
    const int b    = blockIdx.z;
    const int gkv  = h >> 2;

    // ---- Q A-fragments: resident in registers for the whole kernel ----
    uint32_t qh[8][4], ql[8][4];
    {
        const char* qb = (const char*)Qh +
            (((((size_t)(b * PH + h) * 16 + qt) * 8 + w) * 8) * 512) + lane * 16;
        const char* qb2 = (const char*)Ql +
            (((((size_t)(b * PH + h) * 16 + qt) * 8 + w) * 8) * 512) + lane * 16;
        #pragma unroll
        for (int k16 = 0; k16 < 8; k16++) {
            uint4 v = *(const uint4*)(qb + k16 * 512);
            qh[k16][0] = v.x; qh[k16][1] = v.y; qh[k16][2] = v.z; qh[k16][3] = v.w;
            uint4 u = *(const uint4*)(qb2 + k16 * 512);
            ql[k16][0] = u.x; ql[k16][1] = u.y; ql[k16][2] = u.z; ql[k16][3] = u.w;
        }
    }

    float oacc[16][4];
    #pragma unroll
    for (int n = 0; n < 16; n++)
        #pragma unroll
        for (int j = 0; j < 4; j++) oacc[n][j] = 0.0f;
    float m0 = -3.0e38f, m1 = -3.0e38f, l0 = 0.0f, l1 = 0.0f;

    const size_t kvPlane = ((size_t)(b * PHKV + gkv) * 32);
    const char* pKh = (const char*)Kh + kvPlane * 16384;
    const char* pKl = (const char*)Kl + kvPlane * 16384;
    const char* pVh = (const char*)Vh + kvPlane * 16384;
    const char* pVl = (const char*)Vl + kvPlane * 16384;

    const uint32_t sbase = smem_u32(dsm);
    const int t16 = tid * 16;

    // prologue: stage 0
    {
        #pragma unroll
        for (int i = 0; i < 4; i++) {
            const int o = t16 + i * 4096;
            cp16(sbase + o,         pKh + o);
            cp16(sbase + 16384 + o, pKl + o);
            cp16(sbase + 32768 + o, pVh + o);
            cp16(sbase + 49152 + o, pVl + o);
        }
        asm volatile("cp.async.commit_group;" ::: "memory");
    }

    const int r0 = qt * 128 + w * 16 + g;
    const int r1 = r0 + 8;
    const int* mrow0 = mask + (size_t)(b * PS + r0) * PS;
    const int* mrow1 = mask + (size_t)(b * PS + r1) * PS;

    for (int kt = 0; kt < 32; kt++) {
        asm volatile("cp.async.wait_group 0;" ::: "memory");
        __syncthreads();

        if (kt + 1 < 32) {
            const uint32_t dst = sbase + ((kt + 1) & 1) * ATT_STG;
            const size_t go = (size_t)(kt + 1) * 16384;
            #pragma unroll
            for (int i = 0; i < 4; i++) {
                const int o = t16 + i * 4096;
                cp16(dst + o,         pKh + go + o);
                cp16(dst + 16384 + o, pKl + go + o);
                cp16(dst + 32768 + o, pVh + go + o);
                cp16(dst + 49152 + o, pVl + go + o);
            }
            asm volatile("cp.async.commit_group;" ::: "memory");
        }

        const char* stg = dsm + (kt & 1) * ATT_STG;
        const char* sKh = stg;
        const char* sKl = stg + 16384;
        const char* sVh = stg + 32768;
        const char* sVl = stg + 49152;

        // ---- S = Q K^T ----
        float sm[8][4];
        #pragma unroll
        for (int n = 0; n < 8; n++)
            #pragma unroll
            for (int j = 0; j < 4; j++) sm[n][j] = 0.0f;

        #pragma unroll
        for (int k16 = 0; k16 < 8; k16++) {
            uint32_t bh[8][2], bl[8][2];
            #pragma unroll
            for (int n = 0; n < 8; n++) {
                uint2 v = *(const uint2*)(sKh + (n * 8 + k16) * 256 + lane * 8);
                bh[n][0] = v.x; bh[n][1] = v.y;
            }
            #pragma unroll
            for (int n = 0; n < 8; n++)
                mma_bf16(sm[n], qh[k16], bh[n]);
            #pragma unroll
            for (int n = 0; n < 8; n++) {
                uint2 v = *(const uint2*)(sKl + (n * 8 + k16) * 256 + lane * 8);
                bl[n][0] = v.x; bl[n][1] = v.y;
            }
            #pragma unroll
            for (int n = 0; n < 8; n++)
                mma_bf16(sm[n], qh[k16], bl[n]);
            #pragma unroll
            for (int n = 0; n < 8; n++)
                mma_bf16(sm[n], ql[k16], bh[n]);
        }

        // ---- mask + online softmax ----
        const int kc0 = kt * 64 + 2 * t4;
        float mx0 = -3.0e38f, mx1 = -3.0e38f;
        #pragma unroll
        for (int n = 0; n < 8; n++) {
            int2 mv0 = *(const int2*)(mrow0 + kc0 + n * 8);
            int2 mv1 = *(const int2*)(mrow1 + kc0 + n * 8);
            sm[n][0] = mv0.x ? sm[n][0] : -1e9f;
            sm[n][1] = mv0.y ? sm[n][1] : -1e9f;
            sm[n][2] = mv1.x ? sm[n][2] : -1e9f;
            sm[n][3] = mv1.y ? sm[n][3] : -1e9f;
            mx0 = fmaxf(mx0, fmaxf(sm[n][0], sm[n][1]));
            mx1 = fmaxf(mx1, fmaxf(sm[n][2], sm[n][3]));
        }
        #pragma unroll
        for (int off = 1; off <= 2; off <<= 1) {
            mx0 = fmaxf(mx0, __shfl_xor_sync(0xffffffffu, mx0, off, 4));
            mx1 = fmaxf(mx1, __shfl_xor_sync(0xffffffffu, mx1, off, 4));
        }
        const float mn0 = fmaxf(m0, mx0);
        const float mn1 = fmaxf(m1, mx1);
        const float a0 = __expf(m0 - mn0);
        const float a1 = __expf(m1 - mn1);
        m0 = mn0; m1 = mn1;

        float rs0 = 0.0f, rs1 = 0.0f;
        #pragma unroll
        for (int n = 0; n < 8; n++) {
            sm[n][0] = __expf(sm[n][0] - m0); rs0 += sm[n][0];
            sm[n][1] = __expf(sm[n][1] - m0); rs0 += sm[n][1];
            sm[n][2] = __expf(sm[n][2] - m1); rs1 += sm[n][2];
            sm[n][3] = __expf(sm[n][3] - m1); rs1 += sm[n][3];
        }
        #pragma unroll
        for (int off = 1; off <= 2; off <<= 1) {
            rs0 += __shfl_xor_sync(0xffffffffu, rs0, off, 4);
            rs1 += __shfl_xor_sync(0xffffffffu, rs1, off, 4);
        }
        l0 = l0 * a0 + rs0;
        l1 = l1 * a1 + rs1;

        #pragma unroll
        for (int n = 0; n < 16; n++) {
            oacc[n][0] *= a0; oacc[n][1] *= a0;
            oacc[n][2] *= a1; oacc[n][3] *= a1;
        }

        // ---- O += P V ----
        #pragma unroll
        for (int kk = 0; kk < 4; kk++) {
            uint32_t ph[4], pl[4];
            split2(sm[2*kk][0],   sm[2*kk][1],   ph[0], pl[0]);
            split2(sm[2*kk][2],   sm[2*kk][3],   ph[1], pl[1]);
            split2(sm[2*kk+1][0], sm[2*kk+1][1], ph[2], pl[2]);
            split2(sm[2*kk+1][2], sm[2*kk+1][3], ph[3], pl[3]);

            #pragma unroll
            for (int nc = 0; nc < 4; nc++) {
                uint32_t vh[4][2], vl[4][2];
                #pragma unroll
                for (int j = 0; j < 4; j++) {
                    uint2 v = *(const uint2*)(sVh + ((nc*4 + j) * 4 + kk) * 256 + lane * 8);
                    vh[j][0] = v.x; vh[j][1] = v.y;
                    uint2 u = *(const uint2*)(sVl + ((nc*4 + j) * 4 + kk) * 256 + lane * 8);
                    vl[j][0] = u.x; vl[j][1] = u.y;
                }
                #pragma unroll
                for (int j = 0; j < 4; j++)
                    mma_bf16(oacc[nc*4 + j], ph, vh[j]);
                #pragma unroll
                for (int j = 0; j < 4; j++)
                    mma_bf16(oacc[nc*4 + j], ph, vl[j]);
                #pragma unroll
                for (int j = 0; j < 4; j++)
                    mma_bf16(oacc[nc*4 + j], pl, vh[j]);
            }
        }
    }

    // ---- Epilogue ----
    const float inv0 = 1.0f / l0;
    const float inv1 = 1.0f / l1;
    float* c0 = ctx + (size_t)(b * PS + r0) * PD + h * PDH + 2 * t4;
    float* c1 = ctx + (size_t)(b * PS + r1) * PD + h * PDH + 2 * t4;
    #pragma unroll
    for (int n = 0; n < 16; n++) {
        *(float2*)(c0 + n * 8) = make_float2(oacc[n][0] * inv0, oacc[n][1] * inv0);
        *(float2*)(c1 + n * 8) = make_float2(oacc[n][2] * inv1, oacc[n][3] * inv1);
    }
}

// ---------------------------------------------------------------------------
// Launch
// ---------------------------------------------------------------------------
extern "C" void kernel_launch(void* const* d_in, const int* in_sizes, int n_in,
                              void* d_out, int out_size)
{
    (void)in_sizes; (void)n_in; (void)out_size;
    const float* query = (const float*)d_in[0];
    const float* key   = (const float*)d_in[1];
    const float* value = (const float*)d_in[2];
    const int*   mask  = (const int*)  d_in[3];
    const float* Wq    = (const float*)d_in[4];
    const float* Wk    = (const float*)d_in[5];
    const float* Wv    = (const float*)d_in[6];
    const float* Wo    = (const float*)d_in[7];
    float* out = (float*)d_out;

    float *pQ, *pK, *pV, *pCtx;
    cudaGetSymbolAddress((void**)&pQ,   g_Q);
    cudaGetSymbolAddress((void**)&pK,   g_K);
    cudaGetSymbolAddress((void**)&pV,   g_V);
    cudaGetSymbolAddress((void**)&pCtx, g_ctx);

    __nv_bfloat16 *aq_h, *aq_l, *ak_h, *ak_l, *av_h, *av_l, *ac_h, *ac_l;
    __nv_bfloat16 *wq_h, *wq_l, *wk_h, *wk_l, *wv_h, *wv_l, *wo_h, *wo_l;
    __nv_bfloat16 *qa_h, *qa_l, *kb_h, *kb_l, *vb_h, *vb_l;
    cudaGetSymbolAddress((void**)&aq_h, g_aq_h); cudaGetSymbolAddress((void**)&aq_l, g_aq_l);
    cudaGetSymbolAddress((void**)&ak_h, g_ak_h); cudaGetSymbolAddress((void**)&ak_l, g_ak_l);
    cudaGetSymbolAddress((void**)&av_h, g_av_h); cudaGetSymbolAddress((void**)&av_l, g_av_l);
    cudaGetSymbolAddress((void**)&ac_h, g_ac_h); cudaGetSymbolAddress((void**)&ac_l, g_ac_l);
    cudaGetSymbolAddress((void**)&wq_h, g_wq_h); cudaGetSymbolAddress((void**)&wq_l, g_wq_l);
    cudaGetSymbolAddress((void**)&wk_h, g_wk_h); cudaGetSymbolAddress((void**)&wk_l, g_wk_l);
    cudaGetSymbolAddress((void**)&wv_h, g_wv_h); cudaGetSymbolAddress((void**)&wv_l, g_wv_l);
    cudaGetSymbolAddress((void**)&wo_h, g_wo_h); cudaGetSymbolAddress((void**)&wo_l, g_wo_l);
    cudaGetSymbolAddress((void**)&qa_h, g_qa_h); cudaGetSymbolAddress((void**)&qa_l, g_qa_l);
    cudaGetSymbolAddress((void**)&kb_h, g_kb_h); cudaGetSymbolAddress((void**)&kb_l, g_kb_l);
    cudaGetSymbolAddress((void**)&vb_h, g_vb_h); cudaGetSymbolAddress((void**)&vb_l, g_vb_l);

    cudaFuncSetAttribute(tc_gemm, cudaFuncAttributeMaxDynamicSharedMemorySize, GEMM_SMEM);
    cudaFuncSetAttribute(gqa_attn_mma, cudaFuncAttributeMaxDynamicSharedMemorySize, ATT_SMEM);

    const int PACK_A_BLOCKS = (PM * PD / 2) / 256;   // 16384

    // Pack weights
    pack_wT<<<dim3(PD / 32, PD / 32),   dim3(32, 8)>>>(Wq, wq_h, wq_l, PD);
    pack_wT<<<dim3(PKVD / 32, PD / 32), dim3(32, 8)>>>(Wk, wk_h, wk_l, PKVD);
    pack_wT<<<dim3(PKVD / 32, PD / 32), dim3(32, 8)>>>(Wv, wv_h, wv_l, PKVD);
    pack_wT<<<dim3(PD / 32, PD / 32),   dim3(32, 8)>>>(Wo, wo_h, wo_l, PD);

    // Pack activations
    pack_a<<<PACK_A_BLOCKS, 256>>>(query, aq_h, aq_l);
    pack_a<<<PACK_A_BLOCKS, 256>>>(key,   ak_h, ak_l);
    pack_a<<<PACK_A_BLOCKS, 256>>>(value, av_h, av_l);

    // Projections
    tc_gemm<<<dim3(PD / 128,   PM / 128), 256, GEMM_SMEM>>>(aq_h, aq_l, wq_h, wq_l, pQ, PD);
    tc_gemm<<<dim3(PKVD / 128, PM / 128), 256, GEMM_SMEM>>>(ak_h, ak_l, wk_h, wk_l, pK, PKVD);
    tc_gemm<<<dim3(PKVD / 128, PM / 128), 256, GEMM_SMEM>>>(av_h, av_l, wv_h, wv_l, pV, PKVD);

    // Pack attention operands (fragment order)
    pack_qa<<<(PM * PD / 2) / 256, 256>>>(pQ, qa_h, qa_l);
    pack_kb<<<(PM * PKVD / 2) / 256, 256>>>(pK, kb_h, kb_l);
    pack_vb<<<(PM / 2 * PKVD) / 256, 256>>>(pV, vb_h, vb_l);

    // Tensor-core fused attention
    gqa_attn_mma<<<dim3(PS / 128, PH, PB), 256, ATT_SMEM>>>(
        qa_h, qa_l, kb_h, kb_l, vb_h, vb_l, mask, pCtx);

    // Output projection
    pack_a<<<PACK_A_BLOCKS, 256>>>(pCtx, ac_h, ac_l);
    tc_gemm<<<dim3(PD / 128, PM / 128), 256, GEMM_SMEM>>>(ac_h, ac_l, wo_h, wo_l, out, PD);
}

// round 11
// speedup vs baseline: 3.5608x; 1.0916x over previous
#include <cuda_runtime.h>
#include <cuda_bf16.h>
#include <cstdint>

// Problem constants
#define PB   2
#define PS   2048
#define PD   2048
#define PH   16
#define PHKV 4
#define PDH  128
#define PKVD (PHKV * PDH)   // 512
#define PM   (PB * PS)      // 4096
#define NCH  (PD / 16)      // 128 k16-chunks for GEMM

// ---------------------------------------------------------------------------
// Scratch (device globals: no allocations allowed)
// ---------------------------------------------------------------------------
__device__ float g_V[(size_t)PM * PKVD];   // V-proj fp32 (needed for pack_vb pairing)

// GEMM packed planes (fragment order) — validated R7/R8
#define A_PLANE_ELEMS  ((size_t)PM * PD)
#define WQ_PLANE_ELEMS ((size_t)PD * PD)
#define WK_PLANE_ELEMS ((size_t)PD * PKVD)
__device__ __align__(128) __nv_bfloat16 g_aq_h[A_PLANE_ELEMS],  g_aq_l[A_PLANE_ELEMS];
__device__ __align__(128) __nv_bfloat16 g_ak_h[A_PLANE_ELEMS],  g_ak_l[A_PLANE_ELEMS];
__device__ __align__(128) __nv_bfloat16 g_av_h[A_PLANE_ELEMS],  g_av_l[A_PLANE_ELEMS];
__device__ __align__(128) __nv_bfloat16 g_ac_h[A_PLANE_ELEMS],  g_ac_l[A_PLANE_ELEMS];
__device__ __align__(128) __nv_bfloat16 g_wq_h[WQ_PLANE_ELEMS], g_wq_l[WQ_PLANE_ELEMS];
__device__ __align__(128) __nv_bfloat16 g_wo_h[WQ_PLANE_ELEMS], g_wo_l[WQ_PLANE_ELEMS];
__device__ __align__(128) __nv_bfloat16 g_wk_h[WK_PLANE_ELEMS], g_wk_l[WK_PLANE_ELEMS];
__device__ __align__(128) __nv_bfloat16 g_wv_h[WK_PLANE_ELEMS], g_wv_l[WK_PLANE_ELEMS];

// Attention packed planes (fragment order) — validated R8
__device__ __align__(128) __nv_bfloat16 g_qa_h[(size_t)PM * PD],   g_qa_l[(size_t)PM * PD];
__device__ __align__(128) __nv_bfloat16 g_kb_h[(size_t)PM * PKVD], g_kb_l[(size_t)PM * PKVD];
__device__ __align__(128) __nv_bfloat16 g_vb_h[(size_t)PM * PKVD], g_vb_l[(size_t)PM * PKVD];

// ---------------------------------------------------------------------------
// Helpers
// ---------------------------------------------------------------------------
__device__ __forceinline__ uint32_t smem_u32(const void* p) {
    uint32_t a;
    asm("{ .reg .u64 t; cvta.to.shared.u64 t, %1; cvt.u32.u64 %0, t; }"
        : "=r"(a) : "l"(p));
    return a;
}

__device__ __forceinline__ void cp16(uint32_t dst, const void* src) {
    asm volatile("cp.async.cg.shared.global [%0], [%1], 16;"
                 :: "r"(dst), "l"(src) : "memory");
}

__device__ __forceinline__ void mma_bf16(float* c, const uint32_t* a, const uint32_t* b) {
    asm volatile(
        "mma.sync.aligned.m16n8k16.row.col.f32.bf16.bf16.f32 "
        "{%0,%1,%2,%3}, {%4,%5,%6,%7}, {%8,%9}, {%0,%1,%2,%3};"
        : "+f"(c[0]), "+f"(c[1]), "+f"(c[2]), "+f"(c[3])
        : "r"(a[0]), "r"(a[1]), "r"(a[2]), "r"(a[3]),
          "r"(b[0]), "r"(b[1]));
}

// pack two fp32 -> bf16x2 (f0 in low half) + residual pair
__device__ __forceinline__ void split2(float f0, float f1, uint32_t& uh, uint32_t& ul) {
    asm("cvt.rn.bf16x2.f32 %0, %1, %2;" : "=r"(uh) : "f"(f1), "f"(f0));
    float h0 = __uint_as_float(uh << 16);
    float h1 = __uint_as_float(uh & 0xFFFF0000u);
    float l0 = f0 - h0, l1 = f1 - h1;
    asm("cvt.rn.bf16x2.f32 %0, %1, %2;" : "=r"(ul) : "f"(l1), "f"(l0));
}

// ---------------------------------------------------------------------------
// Input pack kernels (validated R7/R8)
// ---------------------------------------------------------------------------
__global__ void pack_a(const float* __restrict__ src,
                       __nv_bfloat16* __restrict__ hi,
                       __nv_bfloat16* __restrict__ lo)
{
    int idx = blockIdx.x * 256 + threadIdx.x;
    int m  = idx >> 10;
    int k  = (idx & 1023) * 2;
    float2 f = ((const float2*)src)[idx];
    uint32_t uh, ul;
    split2(f.x, f.y, uh, ul);

    int R = m >> 7, rr = m & 127;
    int mtile = rr >> 4, r16 = rr & 15;
    int g = r16 & 7, hi8 = r16 >> 3;
    int c = k >> 4, kk = k & 15;
    int t4 = (kk >> 1) & 3, khi = kk >> 3;
    int lane = g * 4 + t4;
    int j = hi8 + 2 * khi;
    size_t off = (((size_t)R * NCH + c) * 8 + mtile) * 512 + lane * 16 + j * 4;
    *(uint32_t*)((char*)hi + off) = uh;
    *(uint32_t*)((char*)lo + off) = ul;
}

__global__ void pack_wT(const float* __restrict__ w,
                        __nv_bfloat16* __restrict__ hi,
                        __nv_bfloat16* __restrict__ lo, int N)
{
    __shared__ float t[32][33];
    const int tx = threadIdx.x, ty = threadIdx.y;
    const int nx = blockIdx.x * 32, k0 = blockIdx.y * 32;

    #pragma unroll
    for (int j = 0; j < 32; j += 8)
        t[ty + j][tx] = w[(size_t)(k0 + ty + j) * N + nx + tx];
    __syncthreads();

    if (tx < 16) {
        const int k  = k0 + 2 * tx;
        const int c  = k >> 4, kk = k & 15;
        const int t4 = (kk >> 1) & 3, khi = kk >> 3;
        #pragma unroll
        for (int j = 0; j < 32; j += 8) {
            const int n = nx + ty + j;
            uint32_t uh, ul;
            split2(t[2 * tx][ty + j], t[2 * tx + 1][ty + j], uh, ul);
            const int NT = n >> 7, nn = n & 127;
            const int ntile = nn >> 3, g = nn & 7;
            const int lane = g * 4 + t4;
            size_t off = (((size_t)NT * NCH + c) * 16 + ntile) * 256 + lane * 8 + khi * 4;
            *(uint32_t*)((char*)hi + off) = uh;
            *(uint32_t*)((char*)lo + off) = ul;
        }
    }
}

// V -> B-fragment planes for PV-mma (n = dh, k = kseq). (validated R8)
__global__ void pack_vb(const float* __restrict__ src,
                        __nv_bfloat16* __restrict__ hi,
                        __nv_bfloat16* __restrict__ lo)
{
    int idx = blockIdx.x * 256 + threadIdx.x;   // over (PM/2)*PKVD
    int rp = idx >> 9;
    int dg = idx & 511;
    int s0 = rp * 2;
    float f0 = src[(size_t)s0 * PKVD + dg];
    float f1 = src[(size_t)(s0 + 1) * PKVD + dg];
    uint32_t uh, ul;
    split2(f0, f1, uh, ul);

    int b = s0 >> 11, s = s0 & 2047;
    int gkv = dg >> 7, d = dg & 127;
    int kt = s >> 6, sk = s & 63;
    int k16 = sk >> 4, kk = sk & 15;
    int t4 = (kk >> 1) & 3, khi = kk >> 3;
    int n8 = d >> 3, gN = d & 7;
    size_t off = ((((size_t)(b * PHKV + gkv) * 32 + kt) * 64) + n8 * 4 + k16) * 256
               + (gN * 4 + t4) * 8 + khi * 4;
    *(uint32_t*)((char*)hi + off) = uh;
    *(uint32_t*)((char*)lo + off) = ul;
}

// ---------------------------------------------------------------------------
// bf16 mma GEMM, 3-term split. 2-chunk stages (32KB), NSTG=3, 64 syncs.
// MODE 0: fp32 C.  MODE 1: split-store to attention Q A-planes (scale folded).
// MODE 2: split-store to attention K B-planes.
// ---------------------------------------------------------------------------
#define GNSTG      3
#define SUB_BYTES  16384
#define GSTG_BYTES 32768
#define GEMM_SMEM  (GNSTG * GSTG_BYTES)   // 98304

template<int MODE>
__global__ __launch_bounds__(256, 1)
void tc_gemm(const __nv_bfloat16* __restrict__ Ah, const __nv_bfloat16* __restrict__ Al,
             const __nv_bfloat16* __restrict__ Bh, const __nv_bfloat16* __restrict__ Bl,
             float* __restrict__ C, __nv_bfloat16* __restrict__ Ph,
             __nv_bfloat16* __restrict__ Pl, int N)
{
    extern __shared__ char dsm[];
    const int tid  = threadIdx.x;
    const int lane = tid & 31;
    const int wid  = tid >> 5;
    const int warp_m = wid >> 2;
    const int warp_n = wid & 3;
    const int mt0 = blockIdx.y, nt0 = blockIdx.x;

    const char* pAh = (const char*)Ah + (size_t)mt0 * NCH * 4096;
    const char* pAl = (const char*)Al + (size_t)mt0 * NCH * 4096;
    const char* pBh = (const char*)Bh + (size_t)nt0 * NCH * 4096;
    const char* pBl = (const char*)Bl + (size_t)nt0 * NCH * 4096;

    const uint32_t sbase = smem_u32(dsm);
    const int t16 = tid * 16;

    // Prologue: fill GNSTG-1 stages (2 chunks each)
    #pragma unroll
    for (int s = 0; s < GNSTG - 1; s++) {
        #pragma unroll
        for (int hf = 0; hf < 2; hf++) {
            const uint32_t d = sbase + s * GSTG_BYTES + hf * SUB_BYTES + t16;
            const size_t o = (size_t)(s * 2 + hf) * 4096 + t16;
            cp16(d,         pAh + o);
            cp16(d + 4096,  pAl + o);
            cp16(d + 8192,  pBh + o);
            cp16(d + 12288, pBl + o);
        }
        asm volatile("cp.async.commit_group;" ::: "memory");
    }

    float acc[4][4][4];
    #pragma unroll
    for (int mt = 0; mt < 4; mt++)
        #pragma unroll
        for (int nt = 0; nt < 4; nt++)
            #pragma unroll
            for (int j = 0; j < 4; j++) acc[mt][nt][j] = 0.0f;

    for (int pc = 0; pc < NCH / 2; pc++) {
        asm volatile("cp.async.wait_group 1;" ::: "memory");
        __syncthreads();

        const int np = pc + GNSTG - 1;
        if (np < NCH / 2) {
            #pragma unroll
            for (int hf = 0; hf < 2; hf++) {
                const uint32_t d = sbase + (np % GNSTG) * GSTG_BYTES + hf * SUB_BYTES + t16;
                const size_t o = (size_t)(np * 2 + hf) * 4096 + t16;
                cp16(d,         pAh + o);
                cp16(d + 4096,  pAl + o);
                cp16(d + 8192,  pBh + o);
                cp16(d + 12288, pBl + o);
            }
        }
        asm volatile("cp.async.commit_group;" ::: "memory");

        #pragma unroll
        for (int hf = 0; hf < 2; hf++) {
            const char* stg = dsm + (pc % GNSTG) * GSTG_BYTES + hf * SUB_BYTES;
            const uint4* sAh = (const uint4*)(stg);
            const uint4* sAl = (const uint4*)(stg + 4096);
            const uint2* sBh = (const uint2*)(stg + 8192);
            const uint2* sBl = (const uint2*)(stg + 12288);

            uint32_t ahi[4][4], alo[4][4], bhi[4][2], blo[4][2];
            #pragma unroll
            for (int mt = 0; mt < 4; mt++) {
                uint4 h = sAh[(warp_m * 4 + mt) * 32 + lane];
                ahi[mt][0] = h.x; ahi[mt][1] = h.y; ahi[mt][2] = h.z; ahi[mt][3] = h.w;
                uint4 l = sAl[(warp_m * 4 + mt) * 32 + lane];
                alo[mt][0] = l.x; alo[mt][1] = l.y; alo[mt][2] = l.z; alo[mt][3] = l.w;
            }
            #pragma unroll
            for (int nt = 0; nt < 4; nt++) {
                uint2 h = sBh[(warp_n * 4 + nt) * 32 + lane];
                bhi[nt][0] = h.x; bhi[nt][1] = h.y;
                uint2 l = sBl[(warp_n * 4 + nt) * 32 + lane];
                blo[nt][0] = l.x; blo[nt][1] = l.y;
            }

            #pragma unroll
            for (int mt = 0; mt < 4; mt++)
                #pragma unroll
                for (int nt = 0; nt < 4; nt++)
                    mma_bf16(acc[mt][nt], ahi[mt], bhi[nt]);
            #pragma unroll
            for (int mt = 0; mt < 4; mt++)
                #pragma unroll
                for (int nt = 0; nt < 4; nt++)
                    mma_bf16(acc[mt][nt], ahi[mt], blo[nt]);
            #pragma unroll
            for (int mt = 0; mt < 4; mt++)
                #pragma unroll
                for (int nt = 0; nt < 4; nt++)
                    mma_bf16(acc[mt][nt], alo[mt], bhi[nt]);
        }
    }

    const int g  = lane >> 2;
    const int t4 = lane & 3;

    #pragma unroll
    for (int mt = 0; mt < 4; mt++) {
        #pragma unroll
        for (int nt = 0; nt < 4; nt++) {
            const int row0 = mt0 * 128 + warp_m * 64 + mt * 16 + g;
            const int col0 = nt0 * 128 + warp_n * 32 + nt * 8 + 2 * t4;

            if (MODE == 0) {
                float* Cp = C + (size_t)row0 * N + col0;
                *(float2*)(Cp)                 = make_float2(acc[mt][nt][0], acc[mt][nt][1]);
                *(float2*)(Cp + (size_t)8 * N) = make_float2(acc[mt][nt][2], acc[mt][nt][3]);
            } else if (MODE == 1) {
                // Q-pack: attention A-fragment planes, scale folded
                const float scale = 0.08838834764831845f;   // 1/sqrt(128)
                const int bb = row0 >> 11, s = row0 & 2047;
                const int qt = s >> 7, rr = s & 127;
                const int wq_ = rr >> 4;
                const int hh = col0 >> 7, d = col0 & 127;
                const int k16 = d >> 4, khi = (d >> 3) & 1;
                size_t base = (((((size_t)(bb * PH + hh) * 16 + qt) * 8 + wq_) * 8 + k16) * 512)
                            + (size_t)(g * 4 + t4) * 16;
                uint32_t uh0, ul0, uh1, ul1;
                split2(acc[mt][nt][0] * scale, acc[mt][nt][1] * scale, uh0, ul0);
                split2(acc[mt][nt][2] * scale, acc[mt][nt][3] * scale, uh1, ul1);
                *(uint32_t*)((char*)Ph + base + (2 * khi) * 4)     = uh0;
                *(uint32_t*)((char*)Ph + base + (1 + 2 * khi) * 4) = uh1;
                *(uint32_t*)((char*)Pl + base + (2 * khi) * 4)     = ul0;
                *(uint32_t*)((char*)Pl + base + (1 + 2 * khi) * 4) = ul1;
            } else {
                // K-pack: attention B-fragment planes
                const int bb = row0 >> 11, s = row0 & 2047;
                const int kt = s >> 6, sk = s & 63;
                const int n8 = sk >> 3;
                const int gkv = col0 >> 7, d = col0 & 127;
                const int k16 = d >> 4, khi = (d >> 3) & 1;
                size_t base = ((((size_t)(bb * PHKV + gkv) * 32 + kt) * 64 + k16) * 256)
                            + (size_t)(g * 4 + t4) * 8 + khi * 4;
                uint32_t uh0, ul0, uh1, ul1;
                split2(acc[mt][nt][0], acc[mt][nt][1], uh0, ul0);
                split2(acc[mt][nt][2], acc[mt][nt][3], uh1, ul1);
                *(uint32_t*)((char*)Ph + base + (size_t)n8 * 2048)       = uh0;
                *(uint32_t*)((char*)Ph + base + (size_t)(n8 + 1) * 2048) = uh1;
                *(uint32_t*)((char*)Pl + base + (size_t)n8 * 2048)       = ul0;
                *(uint32_t*)((char*)Pl + base + (size_t)(n8 + 1) * 2048) = ul1;
            }
        }
    }
}

// ---------------------------------------------------------------------------
// Tensor-core fused GQA flash attention (bf16-S3), 3-stage pipeline.
// Grid (S/128, H, B), 256 threads. Epilogue writes O-proj A-planes directly.
// ---------------------------------------------------------------------------
#define ATT_STG    65536
#define ATT_SMEM   (3 * ATT_STG)   // 196608

__global__ __launch_bounds__(256, 1)
void gqa_attn_mma(const __nv_bfloat16* __restrict__ Qh, const __nv_bfloat16* __restrict__ Ql,
                  const __nv_bfloat16* __restrict__ Kh, const __nv_bfloat16* __restrict__ Kl,
                  const __nv_bfloat16* __restrict__ Vh, const __nv_bfloat16* __restrict__ Vl,
                  const int* __restrict__ mask,
                  __nv_bfloat16* __restrict__ acPh, __nv_bfloat16* __restrict__ acPl)
{
    extern __shared__ char dsm[];
    const int tid  = threadIdx.x;
    const int lane = tid & 31;
    const int w    = tid >> 5;
    const int g    = lane >> 2;
    const int t4   = lane & 3;
    const int qt   = blockIdx.x;
    const int h    = blockIdx.y;
    const int b    = blockIdx.z;
    const int gkv  = h >> 2;

    // Q A-fragments resident in registers
    uint32_t qh[8][4], ql[8][4];
    {
        const size_t qoff = (((((size_t)(b * PH + h) * 16 + qt) * 8 + w) * 8) * 512)
                          + (size_t)lane * 16;
        const char* qb  = (const char*)Qh + qoff;
        const char* qb2 = (const char*)Ql + qoff;
        #pragma unroll
        for (int k16 = 0; k16 < 8; k16++) {
            uint4 v = *(const uint4*)(qb + k16 * 512);
            qh[k16][0] = v.x; qh[k16][1] = v.y; qh[k16][2] = v.z; qh[k16][3] = v.w;
            uint4 u = *(const uint4*)(qb2 + k16 * 512);
            ql[k16][0] = u.x; ql[k16][1] = u.y; ql[k16][2] = u.z; ql[k16][3] = u.w;
        }
    }

    float oacc[16][4];
    #pragma unroll
    for (int n = 0; n < 16; n++)
        #pragma unroll
        for (int j = 0; j < 4; j++) oacc[n][j] = 0.0f;
    float m0 = -3.0e38f, m1 = -3.0e38f, l0 = 0.0f, l1 = 0.0f;

    const size_t kvPlane = ((size_t)(b * PHKV + gkv) * 32);
    const char* pKh = (const char*)Kh + kvPlane * 16384;
    const char* pKl = (const char*)Kl + kvPlane * 16384;
    const char* pVh = (const char*)Vh + kvPlane * 16384;
    const char* pVl = (const char*)Vl + kvPlane * 16384;

    const uint32_t sbase = smem_u32(dsm);
    const int t16 = tid * 16;

    // Prologue: stages 0 and 1
    #pragma unroll
    for (int s = 0; s < 2; s++) {
        const uint32_t dst = sbase + s * ATT_STG;
        const size_t go = (size_t)s * 16384;
        #pragma unroll
        for (int i = 0; i < 4; i++) {
            const int o = t16 + i * 4096;
            cp16(dst + o,         pKh + go + o);
            cp16(dst + 16384 + o, pKl + go + o);
            cp16(dst + 32768 + o, pVh + go + o);
            cp16(dst + 49152 + o, pVl + go + o);
        }
        asm volatile("cp.async.commit_group;" ::: "memory");
    }

    const int r0 = qt * 128 + w * 16 + g;
    const int r1 = r0 + 8;
    const int* mrow0 = mask + (size_t)(b * PS + r0) * PS;
    const int* mrow1 = mask + (size_t)(b * PS + r1) * PS;

    for (int kt = 0; kt < 32; kt++) {
        asm volatile("cp.async.wait_group 1;" ::: "memory");
        __syncthreads();

        if (kt + 2 < 32) {
            const uint32_t dst = sbase + ((kt + 2) % 3) * ATT_STG;
            const size_t go = (size_t)(kt + 2) * 16384;
            #pragma unroll
            for (int i = 0; i < 4; i++) {
                const int o = t16 + i * 4096;
                cp16(dst + o,         pKh + go + o);
                cp16(dst + 16384 + o, pKl + go + o);
                cp16(dst + 32768 + o, pVh + go + o);
                cp16(dst + 49152 + o, pVl + go + o);
            }
        }
        asm volatile("cp.async.commit_group;" ::: "memory");

        const char* stg = dsm + (kt % 3) * ATT_STG;
        const char* sKh = stg;
        const char* sKl = stg + 16384;
        const char* sVh = stg + 32768;
        const char* sVl = stg + 49152;

        // ---- S = Q K^T (3-term) ----
        float sm[8][4];
        #pragma unroll
        for (int n = 0; n < 8; n++)
            #pragma unroll
            for (int j = 0; j < 4; j++) sm[n][j] = 0.0f;

        #pragma unroll
        for (int k16 = 0; k16 < 8; k16++) {
            uint32_t bh[8][2], bl[8][2];
            #pragma unroll
            for (int n = 0; n < 8; n++) {
                uint2 v = *(const uint2*)(sKh + (n * 8 + k16) * 256 + lane * 8);
                bh[n][0] = v.x; bh[n][1] = v.y;
            }
            #pragma unroll
            for (int n = 0; n < 8; n++)
                mma_bf16(sm[n], qh[k16], bh[n]);
            #pragma unroll
            for (int n = 0; n < 8; n++) {
                uint2 v = *(const uint2*)(sKl + (n * 8 + k16) * 256 + lane * 8);
                bl[n][0] = v.x; bl[n][1] = v.y;
            }
            #pragma unroll
            for (int n = 0; n < 8; n++)
                mma_bf16(sm[n], qh[k16], bl[n]);
            #pragma unroll
            for (int n = 0; n < 8; n++)
                mma_bf16(sm[n], ql[k16], bh[n]);
        }

        // ---- mask + online softmax ----
        const int kc0 = kt * 64 + 2 * t4;
        float mx0 = -3.0e38f, mx1 = -3.0e38f;
        #pragma unroll
        for (int n = 0; n < 8; n++) {
            int2 mv0 = *(const int2*)(mrow0 + kc0 + n * 8);
            int2 mv1 = *(const int2*)(mrow1 + kc0 + n * 8);
            sm[n][0] = mv0.x ? sm[n][0] : -1e9f;
            sm[n][1] = mv0.y ? sm[n][1] : -1e9f;
            sm[n][2] = mv1.x ? sm[n][2] : -1e9f;
            sm[n][3] = mv1.y ? sm[n][3] : -1e9f;
            mx0 = fmaxf(mx0, fmaxf(sm[n][0], sm[n][1]));
            mx1 = fmaxf(mx1, fmaxf(sm[n][2], sm[n][3]));
        }
        #pragma unroll
        for (int off = 1; off <= 2; off <<= 1) {
            mx0 = fmaxf(mx0, __shfl_xor_sync(0xffffffffu, mx0, off, 4));
            mx1 = fmaxf(mx1, __shfl_xor_sync(0xffffffffu, mx1, off, 4));
        }
        const float mn0 = fmaxf(m0, mx0);
        const float mn1 = fmaxf(m1, mx1);
        const float a0 = __expf(m0 - mn0);
        const float a1 = __expf(m1 - mn1);
        m0 = mn0; m1 = mn1;

        float rs0 = 0.0f, rs1 = 0.0f;
        #pragma unroll
        for (int n = 0; n < 8; n++) {
            sm[n][0] = __expf(sm[n][0] - m0); rs0 += sm[n][0];
            sm[n][1] = __expf(sm[n][1] - m0); rs0 += sm[n][1];
            sm[n][2] = __expf(sm[n][2] - m1); rs1 += sm[n][2];
            sm[n][3] = __expf(sm[n][3] - m1); rs1 += sm[n][3];
        }
        #pragma unroll
        for (int off = 1; off <= 2; off <<= 1) {
            rs0 += __shfl_xor_sync(0xffffffffu, rs0, off, 4);
            rs1 += __shfl_xor_sync(0xffffffffu, rs1, off, 4);
        }
        l0 = l0 * a0 + rs0;
        l1 = l1 * a1 + rs1;

        #pragma unroll
        for (int n = 0; n < 16; n++) {
            oacc[n][0] *= a0; oacc[n][1] *= a0;
            oacc[n][2] *= a1; oacc[n][3] *= a1;
        }

        // ---- O += P V (3-term) ----
        #pragma unroll
        for (int kk = 0; kk < 4; kk++) {
            uint32_t ph[4], pl[4];
            split2(sm[2*kk][0],   sm[2*kk][1],   ph[0], pl[0]);
            split2(sm[2*kk][2],   sm[2*kk][3],   ph[1], pl[1]);
            split2(sm[2*kk+1][0], sm[2*kk+1][1], ph[2], pl[2]);
            split2(sm[2*kk+1][2], sm[2*kk+1][3], ph[3], pl[3]);

            #pragma unroll
            for (int nc = 0; nc < 4; nc++) {
                uint32_t vh[4][2], vl[4][2];
                #pragma unroll
                for (int j = 0; j < 4; j++) {
                    uint2 v = *(const uint2*)(sVh + ((nc*4 + j) * 4 + kk) * 256 + lane * 8);
                    vh[j][0] = v.x; vh[j][1] = v.y;
                    uint2 u = *(const uint2*)(sVl + ((nc*4 + j) * 4 + kk) * 256 + lane * 8);
                    vl[j][0] = u.x; vl[j][1] = u.y;
                }
                #pragma unroll
                for (int j = 0; j < 4; j++)
                    mma_bf16(oacc[nc*4 + j], ph, vh[j]);
                #pragma unroll
                for (int j = 0; j < 4; j++)
                    mma_bf16(oacc[nc*4 + j], ph, vl[j]);
                #pragma unroll
                for (int j = 0; j < 4; j++)
                    mma_bf16(oacc[nc*4 + j], pl, vh[j]);
            }
        }
    }

    // ---- Epilogue: split-store directly into O-proj A-fragment planes ----
    const float inv0 = 1.0f / l0;
    const float inv1 = 1.0f / l1;
    const size_t cbase = (size_t)(b * 16 + qt) * NCH;
    #pragma unroll
    for (int n = 0; n < 16; n++) {
        const int c = h * 8 + (n >> 1);
        const size_t off = ((cbase + c) * 8 + w) * 512 + (size_t)(g * 4 + t4) * 16;
        uint32_t uh0, ul0, uh1, ul1;
        split2(oacc[n][0] * inv0, oacc[n][1] * inv0, uh0, ul0);
        split2(oacc[n][2] * inv1, oacc[n][3] * inv1, uh1, ul1);
        const int j0 = (2 * (n & 1)) * 4;
        const int j1 = (1 + 2 * (n & 1)) * 4;
        *(uint32_t*)((char*)acPh + off + j0) = uh0;
        *(uint32_t*)((char*)acPh + off + j1) = uh1;
        *(uint32_t*)((char*)acPl + off + j0) = ul0;
        *(uint32_t*)((char*)acPl + off + j1) = ul1;
    }
}

// ---------------------------------------------------------------------------
// Launch
// ---------------------------------------------------------------------------
extern "C" void kernel_launch(void* const* d_in, const int* in_sizes, int n_in,
                              void* d_out, int out_size)
{
    (void)in_sizes; (void)n_in; (void)out_size;
    const float* query = (const float*)d_in[0];
    const float* key   = (const float*)d_in[1];
    const float* value = (const float*)d_in[2];
    const int*   mask  = (const int*)  d_in[3];
    const float* Wq    = (const float*)d_in[4];
    const float* Wk    = (const float*)d_in[5];
    const float* Wv    = (const float*)d_in[6];
    const float* Wo    = (const float*)d_in[7];
    float* out = (float*)d_out;

    float* pV;
    cudaGetSymbolAddress((void**)&pV, g_V);

    __nv_bfloat16 *aq_h, *aq_l, *ak_h, *ak_l, *av_h, *av_l, *ac_h, *ac_l;
    __nv_bfloat16 *wq_h, *wq_l, *wk_h, *wk_l, *wv_h, *wv_l, *wo_h, *wo_l;
    __nv_bfloat16 *qa_h, *qa_l, *kb_h, *kb_l, *vb_h, *vb_l;
    cudaGetSymbolAddress((void**)&aq_h, g_aq_h); cudaGetSymbolAddress((void**)&aq_l, g_aq_l);
    cudaGetSymbolAddress((void**)&ak_h, g_ak_h); cudaGetSymbolAddress((void**)&ak_l, g_ak_l);
    cudaGetSymbolAddress((void**)&av_h, g_av_h); cudaGetSymbolAddress((void**)&av_l, g_av_l);
    cudaGetSymbolAddress((void**)&ac_h, g_ac_h); cudaGetSymbolAddress((void**)&ac_l, g_ac_l);
    cudaGetSymbolAddress((void**)&wq_h, g_wq_h); cudaGetSymbolAddress((void**)&wq_l, g_wq_l);
    cudaGetSymbolAddress((void**)&wk_h, g_wk_h); cudaGetSymbolAddress((void**)&wk_l, g_wk_l);
    cudaGetSymbolAddress((void**)&wv_h, g_wv_h); cudaGetSymbolAddress((void**)&wv_l, g_wv_l);
    cudaGetSymbolAddress((void**)&wo_h, g_wo_h); cudaGetSymbolAddress((void**)&wo_l, g_wo_l);
    cudaGetSymbolAddress((void**)&qa_h, g_qa_h); cudaGetSymbolAddress((void**)&qa_l, g_qa_l);
    cudaGetSymbolAddress((void**)&kb_h, g_kb_h); cudaGetSymbolAddress((void**)&kb_l, g_kb_l);
    cudaGetSymbolAddress((void**)&vb_h, g_vb_h); cudaGetSymbolAddress((void**)&vb_l, g_vb_l);

    cudaFuncSetAttribute(tc_gemm<0>, cudaFuncAttributeMaxDynamicSharedMemorySize, GEMM_SMEM);
    cudaFuncSetAttribute(tc_gemm<1>, cudaFuncAttributeMaxDynamicSharedMemorySize, GEMM_SMEM);
    cudaFuncSetAttribute(tc_gemm<2>, cudaFuncAttributeMaxDynamicSharedMemorySize, GEMM_SMEM);
    cudaFuncSetAttribute(gqa_attn_mma, cudaFuncAttributeMaxDynamicSharedMemorySize, ATT_SMEM);

    const int PACK_A_BLOCKS = (PM * PD / 2) / 256;   // 16384

    // Pack weights
    pack_wT<<<dim3(PD / 32, PD / 32),   dim3(32, 8)>>>(Wq, wq_h, wq_l, PD);
    pack_wT<<<dim3(PKVD / 32, PD / 32), dim3(32, 8)>>>(Wk, wk_h, wk_l, PKVD);
    pack_wT<<<dim3(PKVD / 32, PD / 32), dim3(32, 8)>>>(Wv, wv_h, wv_l, PKVD);
    pack_wT<<<dim3(PD / 32, PD / 32),   dim3(32, 8)>>>(Wo, wo_h, wo_l, PD);

    // Pack input activations
    pack_a<<<PACK_A_BLOCKS, 256>>>(query, aq_h, aq_l);
    pack_a<<<PACK_A_BLOCKS, 256>>>(key,   ak_h, ak_l);
    pack_a<<<PACK_A_BLOCKS, 256>>>(value, av_h, av_l);

    // Projections — Q and K write attention planes directly
    tc_gemm<1><<<dim3(PD / 128,   PM / 128), 256, GEMM_SMEM>>>(
        aq_h, aq_l, wq_h, wq_l, nullptr, qa_h, qa_l, PD);
    tc_gemm<2><<<dim3(PKVD / 128, PM / 128), 256, GEMM_SMEM>>>(
        ak_h, ak_l, wk_h, wk_l, nullptr, kb_h, kb_l, PKVD);
    tc_gemm<0><<<dim3(PKVD / 128, PM / 128), 256, GEMM_SMEM>>>(
        av_h, av_l, wv_h, wv_l, pV, nullptr, nullptr, PKVD);
    pack_vb<<<(PM / 2 * PKVD) / 256, 256>>>(pV, vb_h, vb_l);

    // Tensor-core fused attention — writes O-proj A-planes directly
    gqa_attn_mma<<<dim3(PS / 128, PH, PB), 256, ATT_SMEM>>>(
        qa_h, qa_l, kb_h, kb_l, vb_h, vb_l, mask, ac_h, ac_l);

    // Output projection
    tc_gemm<0><<<dim3(PD / 128, PM / 128), 256, GEMM_SMEM>>>(
        ac_h, ac_l, wo_h, wo_l, out, nullptr, nullptr, PD);
}

// round 12
// speedup vs baseline: 3.6559x; 1.0267x over previous
#include <cuda_runtime.h>
#include <cuda_bf16.h>
#include <cstdint>

// Problem constants
#define PB   2
#define PS   2048
#define PD   2048
#define PH   16
#define PHKV 4
#define PDH  128
#define PKVD (PHKV * PDH)   // 512
#define PM   (PB * PS)      // 4096
#define NCH  (PD / 16)      // 128 k16-chunks for GEMM

// ---------------------------------------------------------------------------
// Scratch (device globals: no allocations allowed)
// ---------------------------------------------------------------------------
__device__ float g_V[(size_t)PM * PKVD];   // V-proj fp32 (needed for pack_vb pairing)

// GEMM packed planes (fragment order) — validated R7/R8
#define A_PLANE_ELEMS  ((size_t)PM * PD)
#define WQ_PLANE_ELEMS ((size_t)PD * PD)
#define WK_PLANE_ELEMS ((size_t)PD * PKVD)
__device__ __align__(128) __nv_bfloat16 g_aq_h[A_PLANE_ELEMS],  g_aq_l[A_PLANE_ELEMS];
__device__ __align__(128) __nv_bfloat16 g_ak_h[A_PLANE_ELEMS],  g_ak_l[A_PLANE_ELEMS];
__device__ __align__(128) __nv_bfloat16 g_av_h[A_PLANE_ELEMS],  g_av_l[A_PLANE_ELEMS];
__device__ __align__(128) __nv_bfloat16 g_ac_h[A_PLANE_ELEMS],  g_ac_l[A_PLANE_ELEMS];
__device__ __align__(128) __nv_bfloat16 g_wq_h[WQ_PLANE_ELEMS], g_wq_l[WQ_PLANE_ELEMS];
__device__ __align__(128) __nv_bfloat16 g_wo_h[WQ_PLANE_ELEMS], g_wo_l[WQ_PLANE_ELEMS];
__device__ __align__(128) __nv_bfloat16 g_wk_h[WK_PLANE_ELEMS], g_wk_l[WK_PLANE_ELEMS];
__device__ __align__(128) __nv_bfloat16 g_wv_h[WK_PLANE_ELEMS], g_wv_l[WK_PLANE_ELEMS];

// Attention packed planes (paired-k16 fragment order)
__device__ __align__(128) __nv_bfloat16 g_qa_h[(size_t)PM * PD],   g_qa_l[(size_t)PM * PD];
__device__ __align__(128) __nv_bfloat16 g_kb_h[(size_t)PM * PKVD], g_kb_l[(size_t)PM * PKVD];
__device__ __align__(128) __nv_bfloat16 g_vb_h[(size_t)PM * PKVD], g_vb_l[(size_t)PM * PKVD];

// ---------------------------------------------------------------------------
// Helpers
// ---------------------------------------------------------------------------
__device__ __forceinline__ uint32_t smem_u32(const void* p) {
    uint32_t a;
    asm("{ .reg .u64 t; cvta.to.shared.u64 t, %1; cvt.u32.u64 %0, t; }"
        : "=r"(a) : "l"(p));
    return a;
}

__device__ __forceinline__ void cp16(uint32_t dst, const void* src) {
    asm volatile("cp.async.cg.shared.global [%0], [%1], 16;"
                 :: "r"(dst), "l"(src) : "memory");
}

__device__ __forceinline__ void mma_bf16(float* c, const uint32_t* a, const uint32_t* b) {
    asm volatile(
        "mma.sync.aligned.m16n8k16.row.col.f32.bf16.bf16.f32 "
        "{%0,%1,%2,%3}, {%4,%5,%6,%7}, {%8,%9}, {%0,%1,%2,%3};"
        : "+f"(c[0]), "+f"(c[1]), "+f"(c[2]), "+f"(c[3])
        : "r"(a[0]), "r"(a[1]), "r"(a[2]), "r"(a[3]),
          "r"(b[0]), "r"(b[1]));
}

__device__ __forceinline__ float ex2f(float x) {
    float r;
    asm("ex2.approx.f32 %0, %1;" : "=f"(r) : "f"(x));
    return r;
}

// pack two fp32 -> bf16x2 (f0 in low half) + residual pair
__device__ __forceinline__ void split2(float f0, float f1, uint32_t& uh, uint32_t& ul) {
    asm("cvt.rn.bf16x2.f32 %0, %1, %2;" : "=r"(uh) : "f"(f1), "f"(f0));
    float h0 = __uint_as_float(uh << 16);
    float h1 = __uint_as_float(uh & 0xFFFF0000u);
    float l0 = f0 - h0, l1 = f1 - h1;
    asm("cvt.rn.bf16x2.f32 %0, %1, %2;" : "=r"(ul) : "f"(l1), "f"(l0));
}

// ---------------------------------------------------------------------------
// Input pack kernels (validated R7/R8)
// ---------------------------------------------------------------------------
__global__ void pack_a(const float* __restrict__ src,
                       __nv_bfloat16* __restrict__ hi,
                       __nv_bfloat16* __restrict__ lo)
{
    int idx = blockIdx.x * 256 + threadIdx.x;
    int m  = idx >> 10;
    int k  = (idx & 1023) * 2;
    float2 f = ((const float2*)src)[idx];
    uint32_t uh, ul;
    split2(f.x, f.y, uh, ul);

    int R = m >> 7, rr = m & 127;
    int mtile = rr >> 4, r16 = rr & 15;
    int g = r16 & 7, hi8 = r16 >> 3;
    int c = k >> 4, kk = k & 15;
    int t4 = (kk >> 1) & 3, khi = kk >> 3;
    int lane = g * 4 + t4;
    int j = hi8 + 2 * khi;
    size_t off = (((size_t)R * NCH + c) * 8 + mtile) * 512 + lane * 16 + j * 4;
    *(uint32_t*)((char*)hi + off) = uh;
    *(uint32_t*)((char*)lo + off) = ul;
}

__global__ void pack_wT(const float* __restrict__ w,
                        __nv_bfloat16* __restrict__ hi,
                        __nv_bfloat16* __restrict__ lo, int N)
{
    __shared__ float t[32][33];
    const int tx = threadIdx.x, ty = threadIdx.y;
    const int nx = blockIdx.x * 32, k0 = blockIdx.y * 32;

    #pragma unroll
    for (int j = 0; j < 32; j += 8)
        t[ty + j][tx] = w[(size_t)(k0 + ty + j) * N + nx + tx];
    __syncthreads();

    if (tx < 16) {
        const int k  = k0 + 2 * tx;
        const int c  = k >> 4, kk = k & 15;
        const int t4 = (kk >> 1) & 3, khi = kk >> 3;
        #pragma unroll
        for (int j = 0; j < 32; j += 8) {
            const int n = nx + ty + j;
            uint32_t uh, ul;
            split2(t[2 * tx][ty + j], t[2 * tx + 1][ty + j], uh, ul);
            const int NT = n >> 7, nn = n & 127;
            const int ntile = nn >> 3, g = nn & 7;
            const int lane = g * 4 + t4;
            size_t off = (((size_t)NT * NCH + c) * 16 + ntile) * 256 + lane * 8 + khi * 4;
            *(uint32_t*)((char*)hi + off) = uh;
            *(uint32_t*)((char*)lo + off) = ul;
        }
    }
}

// V -> B-fragment planes for PV-mma (n = dh, k = kseq), PAIRED k16 layout:
// block (n8, k16p) of 512B: lane*16 + (k16&1)*8 + khi*4
__global__ void pack_vb(const float* __restrict__ src,
                        __nv_bfloat16* __restrict__ hi,
                        __nv_bfloat16* __restrict__ lo)
{
    int idx = blockIdx.x * 256 + threadIdx.x;   // over (PM/2)*PKVD
    int rp = idx >> 9;
    int dg = idx & 511;
    int s0 = rp * 2;
    float f0 = src[(size_t)s0 * PKVD + dg];
    float f1 = src[(size_t)(s0 + 1) * PKVD + dg];
    uint32_t uh, ul;
    split2(f0, f1, uh, ul);

    int b = s0 >> 11, s = s0 & 2047;
    int gkv = dg >> 7, d = dg & 127;
    int kt = s >> 6, sk = s & 63;
    int k16 = sk >> 4, kk = sk & 15;
    int t4 = (kk >> 1) & 3, khi = kk >> 3;
    int n8 = d >> 3, gN = d & 7;
    size_t off = ((size_t)(b * PHKV + gkv) * 32 + kt) * 16384
               + (size_t)(n8 * 2 + (k16 >> 1)) * 512
               + (gN * 4 + t4) * 16 + (k16 & 1) * 8 + khi * 4;
    *(uint32_t*)((char*)hi + off) = uh;
    *(uint32_t*)((char*)lo + off) = ul;
}

// ---------------------------------------------------------------------------
// bf16 mma GEMM, 3-term split. 2-chunk stages, NSTG=3, occupancy 2.
// Phase order hh, lh, (load blo), hl keeps live regs <= 128.
// MODE 0: fp32 C.  MODE 1: attention Q A-planes (scale*log2e folded).
// MODE 2: attention K B-planes (paired-k16 layout).
// ---------------------------------------------------------------------------
#define GNSTG      3
#define SUB_BYTES  16384
#define GSTG_BYTES 32768
#define GEMM_SMEM  (GNSTG * GSTG_BYTES)   // 98304

template<int MODE>
__global__ __launch_bounds__(256, 2)
void tc_gemm(const __nv_bfloat16* __restrict__ Ah, const __nv_bfloat16* __restrict__ Al,
             const __nv_bfloat16* __restrict__ Bh, const __nv_bfloat16* __restrict__ Bl,
             float* __restrict__ C, __nv_bfloat16* __restrict__ Ph,
             __nv_bfloat16* __restrict__ Pl, int N)
{
    extern __shared__ char dsm[];
    const int tid  = threadIdx.x;
    const int lane = tid & 31;
    const int wid  = tid >> 5;
    const int warp_m = wid >> 2;
    const int warp_n = wid & 3;
    const int mt0 = blockIdx.y, nt0 = blockIdx.x;

    const char* pAh = (const char*)Ah + (size_t)mt0 * NCH * 4096;
    const char* pAl = (const char*)Al + (size_t)mt0 * NCH * 4096;
    const char* pBh = (const char*)Bh + (size_t)nt0 * NCH * 4096;
    const char* pBl = (const char*)Bl + (size_t)nt0 * NCH * 4096;

    const uint32_t sbase = smem_u32(dsm);
    const int t16 = tid * 16;

    // Prologue: fill GNSTG-1 stages (2 chunks each)
    #pragma unroll
    for (int s = 0; s < GNSTG - 1; s++) {
        #pragma unroll
        for (int hf = 0; hf < 2; hf++) {
            const uint32_t d = sbase + s * GSTG_BYTES + hf * SUB_BYTES + t16;
            const size_t o = (size_t)(s * 2 + hf) * 4096 + t16;
            cp16(d,         pAh + o);
            cp16(d + 4096,  pAl + o);
            cp16(d + 8192,  pBh + o);
            cp16(d + 12288, pBl + o);
        }
        asm volatile("cp.async.commit_group;" ::: "memory");
    }

    float acc[4][4][4];
    #pragma unroll
    for (int mt = 0; mt < 4; mt++)
        #pragma unroll
        for (int nt = 0; nt < 4; nt++)
            #pragma unroll
            for (int j = 0; j < 4; j++) acc[mt][nt][j] = 0.0f;

    for (int pc = 0; pc < NCH / 2; pc++) {
        asm volatile("cp.async.wait_group 1;" ::: "memory");
        __syncthreads();

        const int np = pc + GNSTG - 1;
        if (np < NCH / 2) {
            #pragma unroll
            for (int hf = 0; hf < 2; hf++) {
                const uint32_t d = sbase + (np % GNSTG) * GSTG_BYTES + hf * SUB_BYTES + t16;
                const size_t o = (size_t)(np * 2 + hf) * 4096 + t16;
                cp16(d,         pAh + o);
                cp16(d + 4096,  pAl + o);
                cp16(d + 8192,  pBh + o);
                cp16(d + 12288, pBl + o);
            }
        }
        asm volatile("cp.async.commit_group;" ::: "memory");

        #pragma unroll
        for (int hf = 0; hf < 2; hf++) {
            const char* stg = dsm + (pc % GNSTG) * GSTG_BYTES + hf * SUB_BYTES;
            const uint4* sAh = (const uint4*)(stg);
            const uint4* sAl = (const uint4*)(stg + 4096);
            const uint2* sBh = (const uint2*)(stg + 8192);
            const uint2* sBl = (const uint2*)(stg + 12288);

            uint32_t ahi[4][4], alo[4][4], bfr[4][2];
            #pragma unroll
            for (int mt = 0; mt < 4; mt++) {
                uint4 h = sAh[(warp_m * 4 + mt) * 32 + lane];
                ahi[mt][0] = h.x; ahi[mt][1] = h.y; ahi[mt][2] = h.z; ahi[mt][3] = h.w;
                uint4 l = sAl[(warp_m * 4 + mt) * 32 + lane];
                alo[mt][0] = l.x; alo[mt][1] = l.y; alo[mt][2] = l.z; alo[mt][3] = l.w;
            }
            // hh + lh with B-hi
            #pragma unroll
            for (int nt = 0; nt < 4; nt++) {
                uint2 h = sBh[(warp_n * 4 + nt) * 32 + lane];
                bfr[nt][0] = h.x; bfr[nt][1] = h.y;
            }
            #pragma unroll
            for (int mt = 0; mt < 4; mt++)
                #pragma unroll
                for (int nt = 0; nt < 4; nt++)
                    mma_bf16(acc[mt][nt], ahi[mt], bfr[nt]);
            #pragma unroll
            for (int mt = 0; mt < 4; mt++)
                #pragma unroll
                for (int nt = 0; nt < 4; nt++)
                    mma_bf16(acc[mt][nt], alo[mt], bfr[nt]);
            // hl with B-lo (reuse bfr regs)
            #pragma unroll
            for (int nt = 0; nt < 4; nt++) {
                uint2 l = sBl[(warp_n * 4 + nt) * 32 + lane];
                bfr[nt][0] = l.x; bfr[nt][1] = l.y;
            }
            #pragma unroll
            for (int mt = 0; mt < 4; mt++)
                #pragma unroll
                for (int nt = 0; nt < 4; nt++)
                    mma_bf16(acc[mt][nt], ahi[mt], bfr[nt]);
        }
    }

    const int g  = lane >> 2;
    const int t4 = lane & 3;

    #pragma unroll
    for (int mt = 0; mt < 4; mt++) {
        #pragma unroll
        for (int nt = 0; nt < 4; nt++) {
            const int row0 = mt0 * 128 + warp_m * 64 + mt * 16 + g;
            const int col0 = nt0 * 128 + warp_n * 32 + nt * 8 + 2 * t4;

            if (MODE == 0) {
                float* Cp = C + (size_t)row0 * N + col0;
                *(float2*)(Cp)                 = make_float2(acc[mt][nt][0], acc[mt][nt][1]);
                *(float2*)(Cp + (size_t)8 * N) = make_float2(acc[mt][nt][2], acc[mt][nt][3]);
            } else if (MODE == 1) {
                // Q-pack: attention A-fragment planes; 1/sqrt(128)*log2(e) folded
                const float scale = 0.08838834764831845f * 1.4426950408889634f;
                const int bb = row0 >> 11, s = row0 & 2047;
                const int qt = s >> 7, rr = s & 127;
                const int wq_ = rr >> 4;
                const int hh = col0 >> 7, d = col0 & 127;
                const int k16 = d >> 4, khi = (d >> 3) & 1;
                size_t base = (((((size_t)(bb * PH + hh) * 16 + qt) * 8 + wq_) * 8 + k16) * 512)
                            + (size_t)(g * 4 + t4) * 16;
                uint32_t uh0, ul0, uh1, ul1;
                split2(acc[mt][nt][0] * scale, acc[mt][nt][1] * scale, uh0, ul0);
                split2(acc[mt][nt][2] * scale, acc[mt][nt][3] * scale, uh1, ul1);
                *(uint32_t*)((char*)Ph + base + (2 * khi) * 4)     = uh0;
                *(uint32_t*)((char*)Ph + base + (1 + 2 * khi) * 4) = uh1;
                *(uint32_t*)((char*)Pl + base + (2 * khi) * 4)     = ul0;
                *(uint32_t*)((char*)Pl + base + (1 + 2 * khi) * 4) = ul1;
            } else {
                // K-pack: attention B-fragment planes, PAIRED k16 layout
                const int bb = row0 >> 11, s = row0 & 2047;
                const int kt = s >> 6, sk = s & 63;
                const int n8 = sk >> 3;
                const int gkv = col0 >> 7, d = col0 & 127;
                const int k16 = d >> 4, khi = (d >> 3) & 1;
                size_t base = ((size_t)(bb * PHKV + gkv) * 32 + kt) * 16384
                            + (size_t)(n8 * 4 + (k16 >> 1)) * 512
                            + (size_t)(g * 4 + t4) * 16 + (k16 & 1) * 8 + khi * 4;
                uint32_t uh0, ul0, uh1, ul1;
                split2(acc[mt][nt][0], acc[mt][nt][1], uh0, ul0);
                split2(acc[mt][nt][2], acc[mt][nt][3], uh1, ul1);
                *(uint32_t*)((char*)Ph + base)        = uh0;
                *(uint32_t*)((char*)Ph + base + 2048) = uh1;   // n8+1
                *(uint32_t*)((char*)Pl + base)        = ul0;
                *(uint32_t*)((char*)Pl + base + 2048) = ul1;
            }
        }
    }
}

// ---------------------------------------------------------------------------
// Tensor-core fused GQA flash attention (bf16-S3), base-2 softmax,
// paired-k16 LDS.128 fragment loads, conditional rescale, 3-stage pipeline.
// ---------------------------------------------------------------------------
#define ATT_STG    65536
#define ATT_SMEM   (3 * ATT_STG)   // 196608

__global__ __launch_bounds__(256, 1)
void gqa_attn_mma(const __nv_bfloat16* __restrict__ Qh, const __nv_bfloat16* __restrict__ Ql,
                  const __nv_bfloat16* __restrict__ Kh, const __nv_bfloat16* __restrict__ Kl,
                  const __nv_bfloat16* __restrict__ Vh, const __nv_bfloat16* __restrict__ Vl,
                  const int* __restrict__ mask,
                  __nv_bfloat16* __restrict__ acPh, __nv_bfloat16* __restrict__ acPl)
{
    extern __shared__ char dsm[];
    const int tid  = threadIdx.x;
    const int lane = tid & 31;
    const int w    = tid >> 5;
    const int g    = lane >> 2;
    const int t4   = lane & 3;
    const int qt   = blockIdx.x;
    const int h    = blockIdx.y;
    const int b    = blockIdx.z;
    const int gkv  = h >> 2;

    // Q A-fragments resident in registers (scores come out in log2 units)
    uint32_t qh[8][4], ql[8][4];
    {
        const size_t qoff = (((((size_t)(b * PH + h) * 16 + qt) * 8 + w) * 8) * 512)
                          + (size_t)lane * 16;
        const char* qb  = (const char*)Qh + qoff;
        const char* qb2 = (const char*)Ql + qoff;
        #pragma unroll
        for (int k16 = 0; k16 < 8; k16++) {
            uint4 v = *(const uint4*)(qb + k16 * 512);
            qh[k16][0] = v.x; qh[k16][1] = v.y; qh[k16][2] = v.z; qh[k16][3] = v.w;
            uint4 u = *(const uint4*)(qb2 + k16 * 512);
            ql[k16][0] = u.x; ql[k16][1] = u.y; ql[k16][2] = u.z; ql[k16][3] = u.w;
        }
    }

    float oacc[16][4];
    #pragma unroll
    for (int n = 0; n < 16; n++)
        #pragma unroll
        for (int j = 0; j < 4; j++) oacc[n][j] = 0.0f;
    float m0 = -3.0e38f, m1 = -3.0e38f, l0 = 0.0f, l1 = 0.0f;

    const size_t kvPlane = ((size_t)(b * PHKV + gkv) * 32);
    const char* pKh = (const char*)Kh + kvPlane * 16384;
    const char* pKl = (const char*)Kl + kvPlane * 16384;
    const char* pVh = (const char*)Vh + kvPlane * 16384;
    const char* pVl = (const char*)Vl + kvPlane * 16384;

    const uint32_t sbase = smem_u32(dsm);
    const int t16 = tid * 16;

    // Prologue: stages 0 and 1
    #pragma unroll
    for (int s = 0; s < 2; s++) {
        const uint32_t dst = sbase + s * ATT_STG;
        const size_t go = (size_t)s * 16384;
        #pragma unroll
        for (int i = 0; i < 4; i++) {
            const int o = t16 + i * 4096;
            cp16(dst + o,         pKh + go + o);
            cp16(dst + 16384 + o, pKl + go + o);
            cp16(dst + 32768 + o, pVh + go + o);
            cp16(dst + 49152 + o, pVl + go + o);
        }
        asm volatile("cp.async.commit_group;" ::: "memory");
    }

    const int r0 = qt * 128 + w * 16 + g;
    const int r1 = r0 + 8;
    const int* mrow0 = mask + (size_t)(b * PS + r0) * PS;
    const int* mrow1 = mask + (size_t)(b * PS + r1) * PS;

    for (int kt = 0; kt < 32; kt++) {
        asm volatile("cp.async.wait_group 1;" ::: "memory");
        __syncthreads();

        if (kt + 2 < 32) {
            const uint32_t dst = sbase + ((kt + 2) % 3) * ATT_STG;
            const size_t go = (size_t)(kt + 2) * 16384;
            #pragma unroll
            for (int i = 0; i < 4; i++) {
                const int o = t16 + i * 4096;
                cp16(dst + o,         pKh + go + o);
                cp16(dst + 16384 + o, pKl + go + o);
                cp16(dst + 32768 + o, pVh + go + o);
                cp16(dst + 49152 + o, pVl + go + o);
            }
        }
        asm volatile("cp.async.commit_group;" ::: "memory");

        const char* stg = dsm + (kt % 3) * ATT_STG;
        const char* sKh = stg;
        const char* sKl = stg + 16384;
        const char* sVh = stg + 32768;
        const char* sVl = stg + 49152;

        // ---- S = Q K^T (3-term), paired-k16 LDS.128 loads ----
        float sm[8][4];
        #pragma unroll
        for (int n = 0; n < 8; n++)
            #pragma unroll
            for (int j = 0; j < 4; j++) sm[n][j] = 0.0f;

        #pragma unroll
        for (int kp = 0; kp < 4; kp++) {
            uint32_t be[8][2], bo[8][2];
            #pragma unroll
            for (int n = 0; n < 8; n++) {
                uint4 v = *(const uint4*)(sKh + (n * 4 + kp) * 512 + lane * 16);
                be[n][0] = v.x; be[n][1] = v.y; bo[n][0] = v.z; bo[n][1] = v.w;
            }
            #pragma unroll
            for (int n = 0; n < 8; n++) mma_bf16(sm[n], qh[2*kp],   be[n]);
            #pragma unroll
            for (int n = 0; n < 8; n++) mma_bf16(sm[n], qh[2*kp+1], bo[n]);
            #pragma unroll
            for (int n = 0; n < 8; n++) mma_bf16(sm[n], ql[2*kp],   be[n]);
            #pragma unroll
            for (int n = 0; n < 8; n++) mma_bf16(sm[n], ql[2*kp+1], bo[n]);
            #pragma unroll
            for (int n = 0; n < 8; n++) {
                uint4 u = *(const uint4*)(sKl + (n * 4 + kp) * 512 + lane * 16);
                be[n][0] = u.x; be[n][1] = u.y; bo[n][0] = u.z; bo[n][1] = u.w;
            }
            #pragma unroll
            for (int n = 0; n < 8; n++) mma_bf16(sm[n], qh[2*kp],   be[n]);
            #pragma unroll
            for (int n = 0; n < 8; n++) mma_bf16(sm[n], qh[2*kp+1], bo[n]);
        }

        // ---- mask + online softmax (base-2) ----
        const int kc0 = kt * 64 + 2 * t4;
        float mx0 = -3.0e38f, mx1 = -3.0e38f;
        #pragma unroll
        for (int n = 0; n < 8; n++) {
            int2 mv0 = *(const int2*)(mrow0 + kc0 + n * 8);
            int2 mv1 = *(const int2*)(mrow1 + kc0 + n * 8);
            sm[n][0] = mv0.x ? sm[n][0] : -1e9f;
            sm[n][1] = mv0.y ? sm[n][1] : -1e9f;
            sm[n][2] = mv1.x ? sm[n][2] : -1e9f;
            sm[n][3] = mv1.y ? sm[n][3] : -1e9f;
            mx0 = fmaxf(mx0, fmaxf(sm[n][0], sm[n][1]));
            mx1 = fmaxf(mx1, fmaxf(sm[n][2], sm[n][3]));
        }
        #pragma unroll
        for (int off = 1; off <= 2; off <<= 1) {
            mx0 = fmaxf(mx0, __shfl_xor_sync(0xffffffffu, mx0, off, 4));
            mx1 = fmaxf(mx1, __shfl_xor_sync(0xffffffffu, mx1, off, 4));
        }
        const float mn0 = fmaxf(m0, mx0);
        const float mn1 = fmaxf(m1, mx1);
        const float a0 = ex2f(m0 - mn0);
        const float a1 = ex2f(m1 - mn1);
        m0 = mn0; m1 = mn1;

        float rs0 = 0.0f, rs1 = 0.0f;
        #pragma unroll
        for (int n = 0; n < 8; n++) {
            sm[n][0] = ex2f(sm[n][0] - m0); rs0 += sm[n][0];
            sm[n][1] = ex2f(sm[n][1] - m0); rs0 += sm[n][1];
            sm[n][2] = ex2f(sm[n][2] - m1); rs1 += sm[n][2];
            sm[n][3] = ex2f(sm[n][3] - m1); rs1 += sm[n][3];
        }
        #pragma unroll
        for (int off = 1; off <= 2; off <<= 1) {
            rs0 += __shfl_xor_sync(0xffffffffu, rs0, off, 4);
            rs1 += __shfl_xor_sync(0xffffffffu, rs1, off, 4);
        }
        l0 = l0 * a0 + rs0;
        l1 = l1 * a1 + rs1;

        // rescale only if some row's max moved (warp-uniform branch)
        if (__any_sync(0xffffffffu, (a0 != 1.0f) || (a1 != 1.0f))) {
            #pragma unroll
            for (int n = 0; n < 16; n++) {
                oacc[n][0] *= a0; oacc[n][1] *= a0;
                oacc[n][2] *= a1; oacc[n][3] *= a1;
            }
        }

        // ---- O += P V (3-term), paired-k16 LDS.128 loads ----
        #pragma unroll
        for (int kp = 0; kp < 2; kp++) {
            uint32_t phe[4], ple[4], pho[4], plo[4];
            split2(sm[4*kp][0],   sm[4*kp][1],   phe[0], ple[0]);
            split2(sm[4*kp][2],   sm[4*kp][3],   phe[1], ple[1]);
            split2(sm[4*kp+1][0], sm[4*kp+1][1], phe[2], ple[2]);
            split2(sm[4*kp+1][2], sm[4*kp+1][3], phe[3], ple[3]);
            split2(sm[4*kp+2][0], sm[4*kp+2][1], pho[0], plo[0]);
            split2(sm[4*kp+2][2], sm[4*kp+2][3], pho[1], plo[1]);
            split2(sm[4*kp+3][0], sm[4*kp+3][1], pho[2], plo[2]);
            split2(sm[4*kp+3][2], sm[4*kp+3][3], pho[3], plo[3]);

            #pragma unroll
            for (int ng = 0; ng < 4; ng++) {
                uint32_t ve[4][2], vo[4][2];
                #pragma unroll
                for (int j = 0; j < 4; j++) {
                    uint4 v = *(const uint4*)(sVh + ((ng*4 + j) * 2 + kp) * 512 + lane * 16);
                    ve[j][0] = v.x; ve[j][1] = v.y; vo[j][0] = v.z; vo[j][1] = v.w;
                }
                #pragma unroll
                for (int j = 0; j < 4; j++) mma_bf16(oacc[ng*4 + j], phe, ve[j]);
                #pragma unroll
                for (int j = 0; j < 4; j++) mma_bf16(oacc[ng*4 + j], pho, vo[j]);
                #pragma unroll
                for (int j = 0; j < 4; j++) mma_bf16(oacc[ng*4 + j], ple, ve[j]);
                #pragma unroll
                for (int j = 0; j < 4; j++) mma_bf16(oacc[ng*4 + j], plo, vo[j]);
            }
            #pragma unroll
            for (int ng = 0; ng < 4; ng++) {
                uint32_t ue[4][2], uo[4][2];
                #pragma unroll
                for (int j = 0; j < 4; j++) {
                    uint4 u = *(const uint4*)(sVl + ((ng*4 + j) * 2 + kp) * 512 + lane * 16);
                    ue[j][0] = u.x; ue[j][1] = u.y; uo[j][0] = u.z; uo[j][1] = u.w;
                }
                #pragma unroll
                for (int j = 0; j < 4; j++) mma_bf16(oacc[ng*4 + j], phe, ue[j]);
                #pragma unroll
                for (int j = 0; j < 4; j++) mma_bf16(oacc[ng*4 + j], pho, uo[j]);
            }
        }
    }

    // ---- Epilogue: split-store directly into O-proj A-fragment planes ----
    const float inv0 = 1.0f / l0;
    const float inv1 = 1.0f / l1;
    const size_t cbase = (size_t)(b * 16 + qt) * NCH;
    #pragma unroll
    for (int n = 0; n < 16; n++) {
        const int c = h * 8 + (n >> 1);
        const size_t off = ((cbase + c) * 8 + w) * 512 + (size_t)(g * 4 + t4) * 16;
        uint32_t uh0, ul0, uh1, ul1;
        split2(oacc[n][0] * inv0, oacc[n][1] * inv0, uh0, ul0);
        split2(oacc[n][2] * inv1, oacc[n][3] * inv1, uh1, ul1);
        const int j0 = (2 * (n & 1)) * 4;
        const int j1 = (1 + 2 * (n & 1)) * 4;
        *(uint32_t*)((char*)acPh + off + j0) = uh0;
        *(uint32_t*)((char*)acPh + off + j1) = uh1;
        *(uint32_t*)((char*)acPl + off + j0) = ul0;
        *(uint32_t*)((char*)acPl + off + j1) = ul1;
    }
}

// ---------------------------------------------------------------------------
// Launch
// ---------------------------------------------------------------------------
extern "C" void kernel_launch(void* const* d_in, const int* in_sizes, int n_in,
                              void* d_out, int out_size)
{
    (void)in_sizes; (void)n_in; (void)out_size;
    const float* query = (const float*)d_in[0];
    const float* key   = (const float*)d_in[1];
    const float* value = (const float*)d_in[2];
    const int*   mask  = (const int*)  d_in[3];
    const float* Wq    = (const float*)d_in[4];
    const float* Wk    = (const float*)d_in[5];
    const float* Wv    = (const float*)d_in[6];
    const float* Wo    = (const float*)d_in[7];
    float* out = (float*)d_out;

    float* pV;
    cudaGetSymbolAddress((void**)&pV, g_V);

    __nv_bfloat16 *aq_h, *aq_l, *ak_h, *ak_l, *av_h, *av_l, *ac_h, *ac_l;
    __nv_bfloat16 *wq_h, *wq_l, *wk_h, *wk_l, *wv_h, *wv_l, *wo_h, *wo_l;
    __nv_bfloat16 *qa_h, *qa_l, *kb_h, *kb_l, *vb_h, *vb_l;
    cudaGetSymbolAddress((void**)&aq_h, g_aq_h); cudaGetSymbolAddress((void**)&aq_l, g_aq_l);
    cudaGetSymbolAddress((void**)&ak_h, g_ak_h); cudaGetSymbolAddress((void**)&ak_l, g_ak_l);
    cudaGetSymbolAddress((void**)&av_h, g_av_h); cudaGetSymbolAddress((void**)&av_l, g_av_l);
    cudaGetSymbolAddress((void**)&ac_h, g_ac_h); cudaGetSymbolAddress((void**)&ac_l, g_ac_l);
    cudaGetSymbolAddress((void**)&wq_h, g_wq_h); cudaGetSymbolAddress((void**)&wq_l, g_wq_l);
    cudaGetSymbolAddress((void**)&wk_h, g_wk_h); cudaGetSymbolAddress((void**)&wk_l, g_wk_l);
    cudaGetSymbolAddress((void**)&wv_h, g_wv_h); cudaGetSymbolAddress((void**)&wv_l, g_wv_l);
    cudaGetSymbolAddress((void**)&wo_h, g_wo_h); cudaGetSymbolAddress((void**)&wo_l, g_wo_l);
    cudaGetSymbolAddress((void**)&qa_h, g_qa_h); cudaGetSymbolAddress((void**)&qa_l, g_qa_l);
    cudaGetSymbolAddress((void**)&kb_h, g_kb_h); cudaGetSymbolAddress((void**)&kb_l, g_kb_l);
    cudaGetSymbolAddress((void**)&vb_h, g_vb_h); cudaGetSymbolAddress((void**)&vb_l, g_vb_l);

    cudaFuncSetAttribute(tc_gemm<0>, cudaFuncAttributeMaxDynamicSharedMemorySize, GEMM_SMEM);
    cudaFuncSetAttribute(tc_gemm<1>, cudaFuncAttributeMaxDynamicSharedMemorySize, GEMM_SMEM);
    cudaFuncSetAttribute(tc_gemm<2>, cudaFuncAttributeMaxDynamicSharedMemorySize, GEMM_SMEM);
    cudaFuncSetAttribute(gqa_attn_mma, cudaFuncAttributeMaxDynamicSharedMemorySize, ATT_SMEM);

    const int PACK_A_BLOCKS = (PM * PD / 2) / 256;   // 16384

    // Pack weights
    pack_wT<<<dim3(PD / 32, PD / 32),   dim3(32, 8)>>>(Wq, wq_h, wq_l, PD);
    pack_wT<<<dim3(PKVD / 32, PD / 32), dim3(32, 8)>>>(Wk, wk_h, wk_l, PKVD);
    pack_wT<<<dim3(PKVD / 32, PD / 32), dim3(32, 8)>>>(Wv, wv_h, wv_l, PKVD);
    pack_wT<<<dim3(PD / 32, PD / 32),   dim3(32, 8)>>>(Wo, wo_h, wo_l, PD);

    // Pack input activations
    pack_a<<<PACK_A_BLOCKS, 256>>>(query, aq_h, aq_l);
    pack_a<<<PACK_A_BLOCKS, 256>>>(key,   ak_h, ak_l);
    pack_a<<<PACK_A_BLOCKS, 256>>>(value, av_h, av_l);

    // Projections — Q and K write attention planes directly
    tc_gemm<1><<<dim3(PD / 128,   PM / 128), 256, GEMM_SMEM>>>(
        aq_h, aq_l, wq_h, wq_l, nullptr, qa_h, qa_l, PD);
    tc_gemm<2><<<dim3(PKVD / 128, PM / 128), 256, GEMM_SMEM>>>(
        ak_h, ak_l, wk_h, wk_l, nullptr, kb_h, kb_l, PKVD);
    tc_gemm<0><<<dim3(PKVD / 128, PM / 128), 256, GEMM_SMEM>>>(
        av_h, av_l, wv_h, wv_l, pV, nullptr, nullptr, PKVD);
    pack_vb<<<(PM / 2 * PKVD) / 256, 256>>>(pV, vb_h, vb_l);

    // Tensor-core fused attention — writes O-proj A-planes directly
    gqa_attn_mma<<<dim3(PS / 128, PH, PB), 256, ATT_SMEM>>>(
        qa_h, qa_l, kb_h, kb_l, vb_h, vb_l, mask, ac_h, ac_l);

    // Output projection
    tc_gemm<0><<<dim3(PD / 128, PM / 128), 256, GEMM_SMEM>>>(
        ac_h, ac_l, wo_h, wo_l, out, nullptr, nullptr, PD);
}

// round 13
// speedup vs baseline: 3.8018x; 1.0399x over previous
#include <cuda_runtime.h>
#include <cuda_bf16.h>
#include <cstdint>

// Problem constants
#define PB   2
#define PS   2048
#define PD   2048
#define PH   16
#define PHKV 4
#define PDH  128
#define PKVD (PHKV * PDH)   // 512
#define PM   (PB * PS)      // 4096
#define NCH  (PD / 16)      // 128 k16-chunks for GEMM

// ---------------------------------------------------------------------------
// Scratch (device globals: no allocations allowed)
// ---------------------------------------------------------------------------
__device__ float g_V[(size_t)PM * PKVD];   // V-proj fp32 (needed for pack_vb pairing)

// GEMM packed planes (fragment order) — validated R7/R8
#define A_PLANE_ELEMS  ((size_t)PM * PD)
#define WQ_PLANE_ELEMS ((size_t)PD * PD)
#define WK_PLANE_ELEMS ((size_t)PD * PKVD)
__device__ __align__(128) __nv_bfloat16 g_aq_h[A_PLANE_ELEMS],  g_aq_l[A_PLANE_ELEMS];
__device__ __align__(128) __nv_bfloat16 g_ak_h[A_PLANE_ELEMS],  g_ak_l[A_PLANE_ELEMS];
__device__ __align__(128) __nv_bfloat16 g_av_h[A_PLANE_ELEMS],  g_av_l[A_PLANE_ELEMS];
__device__ __align__(128) __nv_bfloat16 g_ac_h[A_PLANE_ELEMS],  g_ac_l[A_PLANE_ELEMS];
__device__ __align__(128) __nv_bfloat16 g_wq_h[WQ_PLANE_ELEMS], g_wq_l[WQ_PLANE_ELEMS];
__device__ __align__(128) __nv_bfloat16 g_wo_h[WQ_PLANE_ELEMS], g_wo_l[WQ_PLANE_ELEMS];
__device__ __align__(128) __nv_bfloat16 g_wk_h[WK_PLANE_ELEMS], g_wk_l[WK_PLANE_ELEMS];
__device__ __align__(128) __nv_bfloat16 g_wv_h[WK_PLANE_ELEMS], g_wv_l[WK_PLANE_ELEMS];

// Attention packed planes (paired-k16 fragment order)
__device__ __align__(128) __nv_bfloat16 g_qa_h[(size_t)PM * PD],   g_qa_l[(size_t)PM * PD];
__device__ __align__(128) __nv_bfloat16 g_kb_h[(size_t)PM * PKVD], g_kb_l[(size_t)PM * PKVD];
__device__ __align__(128) __nv_bfloat16 g_vb_h[(size_t)PM * PKVD], g_vb_l[(size_t)PM * PKVD];

// ---------------------------------------------------------------------------
// Helpers
// ---------------------------------------------------------------------------
__device__ __forceinline__ uint32_t smem_u32(const void* p) {
    uint32_t a;
    asm("{ .reg .u64 t; cvta.to.shared.u64 t, %1; cvt.u32.u64 %0, t; }"
        : "=r"(a) : "l"(p));
    return a;
}

__device__ __forceinline__ void cp16(uint32_t dst, const void* src) {
    asm volatile("cp.async.cg.shared.global [%0], [%1], 16;"
                 :: "r"(dst), "l"(src) : "memory");
}

__device__ __forceinline__ void mma_bf16(float* c, const uint32_t* a, const uint32_t* b) {
    asm volatile(
        "mma.sync.aligned.m16n8k16.row.col.f32.bf16.bf16.f32 "
        "{%0,%1,%2,%3}, {%4,%5,%6,%7}, {%8,%9}, {%0,%1,%2,%3};"
        : "+f"(c[0]), "+f"(c[1]), "+f"(c[2]), "+f"(c[3])
        : "r"(a[0]), "r"(a[1]), "r"(a[2]), "r"(a[3]),
          "r"(b[0]), "r"(b[1]));
}

__device__ __forceinline__ float ex2f(float x) {
    float r;
    asm("ex2.approx.f32 %0, %1;" : "=f"(r) : "f"(x));
    return r;
}

// pack two fp32 -> bf16x2 (f0 in low half) + residual pair
__device__ __forceinline__ void split2(float f0, float f1, uint32_t& uh, uint32_t& ul) {
    asm("cvt.rn.bf16x2.f32 %0, %1, %2;" : "=r"(uh) : "f"(f1), "f"(f0));
    float h0 = __uint_as_float(uh << 16);
    float h1 = __uint_as_float(uh & 0xFFFF0000u);
    float l0 = f0 - h0, l1 = f1 - h1;
    asm("cvt.rn.bf16x2.f32 %0, %1, %2;" : "=r"(ul) : "f"(l1), "f"(l0));
}

// ---------------------------------------------------------------------------
// pack_a3: q/k/v inputs -> A-fragment hi/lo planes, one launch.
// Each thread: rows (m, m+8) x one k-pair -> one uint2 per plane.
// ---------------------------------------------------------------------------
#define PACKA_BLOCKS_PER 8192   // (PM*PD/4)/256

__global__ void pack_a3(const float* __restrict__ q, const float* __restrict__ k,
                        const float* __restrict__ v,
                        __nv_bfloat16* __restrict__ qhp, __nv_bfloat16* __restrict__ qlp,
                        __nv_bfloat16* __restrict__ khp, __nv_bfloat16* __restrict__ klp,
                        __nv_bfloat16* __restrict__ vhp, __nv_bfloat16* __restrict__ vlp)
{
    const int which = blockIdx.x >> 13;            // 0,1,2
    const int inner = blockIdx.x & 8191;
    const float* src = (which == 0) ? q : (which == 1) ? k : v;
    __nv_bfloat16* hi = (which == 0) ? qhp : (which == 1) ? khp : vhp;
    __nv_bfloat16* lo = (which == 0) ? qlp : (which == 1) ? klp : vlp;

    int idx = inner * 256 + threadIdx.x;           // over PM*PD/4
    int c2 = idx & 1023;
    int mg = idx >> 10;
    int g  = mg & 7;
    int mt = (mg >> 3) & 7;
    int R  = mg >> 6;
    int m  = R * 128 + mt * 16 + g;                // row (hi8=0); pair is m+8
    int kcol = c2 * 2;
    int c  = kcol >> 4, kk = kcol & 15;
    int t4 = (kk >> 1) & 3, khi = kk >> 3;

    float2 f0 = ((const float2*)(src + (size_t)m * PD))[c2];
    float2 f1 = ((const float2*)(src + (size_t)(m + 8) * PD))[c2];
    uint32_t uh0, ul0, uh1, ul1;
    split2(f0.x, f0.y, uh0, ul0);
    split2(f1.x, f1.y, uh1, ul1);

    size_t off = (((size_t)R * NCH + c) * 8 + mt) * 512
               + (size_t)(g * 4 + t4) * 16 + khi * 8;
    *(uint2*)((char*)hi + off) = make_uint2(uh0, uh1);
    *(uint2*)((char*)lo + off) = make_uint2(ul0, ul1);
}

__global__ void pack_wT(const float* __restrict__ w,
                        __nv_bfloat16* __restrict__ hi,
                        __nv_bfloat16* __restrict__ lo, int N)
{
    __shared__ float t[32][33];
    const int tx = threadIdx.x, ty = threadIdx.y;
    const int nx = blockIdx.x * 32, k0 = blockIdx.y * 32;

    #pragma unroll
    for (int j = 0; j < 32; j += 8)
        t[ty + j][tx] = w[(size_t)(k0 + ty + j) * N + nx + tx];
    __syncthreads();

    if (tx < 16) {
        const int k  = k0 + 2 * tx;
        const int c  = k >> 4, kk = k & 15;
        const int t4 = (kk >> 1) & 3, khi = kk >> 3;
        #pragma unroll
        for (int j = 0; j < 32; j += 8) {
            const int n = nx + ty + j;
            uint32_t uh, ul;
            split2(t[2 * tx][ty + j], t[2 * tx + 1][ty + j], uh, ul);
            const int NT = n >> 7, nn = n & 127;
            const int ntile = nn >> 3, g = nn & 7;
            const int lane = g * 4 + t4;
            size_t off = (((size_t)NT * NCH + c) * 16 + ntile) * 256 + lane * 8 + khi * 4;
            *(uint32_t*)((char*)hi + off) = uh;
            *(uint32_t*)((char*)lo + off) = ul;
        }
    }
}

// V -> B-fragment planes for PV-mma (n = dh, k = kseq), PAIRED k16 layout
__global__ void pack_vb(const float* __restrict__ src,
                        __nv_bfloat16* __restrict__ hi,
                        __nv_bfloat16* __restrict__ lo)
{
    int idx = blockIdx.x * 256 + threadIdx.x;   // over (PM/2)*PKVD
    int rp = idx >> 9;
    int dg = idx & 511;
    int s0 = rp * 2;
    float f0 = src[(size_t)s0 * PKVD + dg];
    float f1 = src[(size_t)(s0 + 1) * PKVD + dg];
    uint32_t uh, ul;
    split2(f0, f1, uh, ul);

    int b = s0 >> 11, s = s0 & 2047;
    int gkv = dg >> 7, d = dg & 127;
    int kt = s >> 6, sk = s & 63;
    int k16 = sk >> 4, kk = sk & 15;
    int t4 = (kk >> 1) & 3, khi = kk >> 3;
    int n8 = d >> 3, gN = d & 7;
    size_t off = ((size_t)(b * PHKV + gkv) * 32 + kt) * 16384
               + (size_t)(n8 * 2 + (k16 >> 1)) * 512
               + (gN * 4 + t4) * 16 + (k16 & 1) * 8 + khi * 4;
    *(uint32_t*)((char*)hi + off) = uh;
    *(uint32_t*)((char*)lo + off) = ul;
}

// ---------------------------------------------------------------------------
// GEMM mainloop body shared by qkv_gemm and tc_gemm (macro to keep regs tight)
// ---------------------------------------------------------------------------
#define GNSTG      3
#define SUB_BYTES  16384
#define GSTG_BYTES 32768
#define GEMM_SMEM  (GNSTG * GSTG_BYTES)   // 98304

#define GEMM_MAINLOOP()                                                         \
    const uint32_t sbase = smem_u32(dsm);                                       \
    const int t16 = tid * 16;                                                   \
    _Pragma("unroll")                                                           \
    for (int s = 0; s < GNSTG - 1; s++) {                                       \
        _Pragma("unroll")                                                       \
        for (int hf = 0; hf < 2; hf++) {                                        \
            const uint32_t d = sbase + s * GSTG_BYTES + hf * SUB_BYTES + t16;   \
            const size_t o = (size_t)(s * 2 + hf) * 4096 + t16;                 \
            cp16(d,         pAh + o);                                           \
            cp16(d + 4096,  pAl + o);                                           \
            cp16(d + 8192,  pBh + o);                                           \
            cp16(d + 12288, pBl + o);                                           \
        }                                                                       \
        asm volatile("cp.async.commit_group;" ::: "memory");                    \
    }                                                                           \
    _Pragma("unroll")                                                           \
    for (int mt = 0; mt < 4; mt++)                                              \
        _Pragma("unroll")                                                       \
        for (int nt = 0; nt < 4; nt++)                                          \
            _Pragma("unroll")                                                   \
            for (int j = 0; j < 4; j++) acc[mt][nt][j] = 0.0f;                  \
    for (int pc = 0; pc < NCH / 2; pc++) {                                      \
        asm volatile("cp.async.wait_group 1;" ::: "memory");                    \
        __syncthreads();                                                        \
        const int np = pc + GNSTG - 1;                                          \
        if (np < NCH / 2) {                                                     \
            _Pragma("unroll")                                                   \
            for (int hf = 0; hf < 2; hf++) {                                    \
                const uint32_t d = sbase + (np % GNSTG) * GSTG_BYTES            \
                                 + hf * SUB_BYTES + t16;                        \
                const size_t o = (size_t)(np * 2 + hf) * 4096 + t16;            \
                cp16(d,         pAh + o);                                       \
                cp16(d + 4096,  pAl + o);                                       \
                cp16(d + 8192,  pBh + o);                                       \
                cp16(d + 12288, pBl + o);                                       \
            }                                                                   \
        }                                                                       \
        asm volatile("cp.async.commit_group;" ::: "memory");                    \
        _Pragma("unroll")                                                       \
        for (int hf = 0; hf < 2; hf++) {                                        \
            const char* stg = dsm + (pc % GNSTG) * GSTG_BYTES + hf * SUB_BYTES; \
            const uint4* sAh = (const uint4*)(stg);                             \
            const uint4* sAl = (const uint4*)(stg + 4096);                      \
            const uint2* sBh = (const uint2*)(stg + 8192);                      \
            const uint2* sBl = (const uint2*)(stg + 12288);                     \
            uint32_t ahi[4][4], alo[4][4], bfr[4][2];                           \
            _Pragma("unroll")                                                   \
            for (int mt = 0; mt < 4; mt++) {                                    \
                uint4 h = sAh[(warp_m * 4 + mt) * 32 + lane];                   \
                ahi[mt][0] = h.x; ahi[mt][1] = h.y;                             \
                ahi[mt][2] = h.z; ahi[mt][3] = h.w;                             \
                uint4 l = sAl[(warp_m * 4 + mt) * 32 + lane];                   \
                alo[mt][0] = l.x; alo[mt][1] = l.y;                             \
                alo[mt][2] = l.z; alo[mt][3] = l.w;                             \
            }                                                                   \
            _Pragma("unroll")                                                   \
            for (int nt = 0; nt < 4; nt++) {                                    \
                uint2 h = sBh[(warp_n * 4 + nt) * 32 + lane];                   \
                bfr[nt][0] = h.x; bfr[nt][1] = h.y;                             \
            }                                                                   \
            _Pragma("unroll")                                                   \
            for (int mt = 0; mt < 4; mt++)                                      \
                _Pragma("unroll")                                               \
                for (int nt = 0; nt < 4; nt++)                                  \
                    mma_bf16(acc[mt][nt], ahi[mt], bfr[nt]);                    \
            _Pragma("unroll")                                                   \
            for (int mt = 0; mt < 4; mt++)                                      \
                _Pragma("unroll")                                               \
                for (int nt = 0; nt < 4; nt++)                                  \
                    mma_bf16(acc[mt][nt], alo[mt], bfr[nt]);                    \
            _Pragma("unroll")                                                   \
            for (int nt = 0; nt < 4; nt++) {                                    \
                uint2 l = sBl[(warp_n * 4 + nt) * 32 + lane];                   \
                bfr[nt][0] = l.x; bfr[nt][1] = l.y;                             \
            }                                                                   \
            _Pragma("unroll")                                                   \
            for (int mt = 0; mt < 4; mt++)                                      \
                _Pragma("unroll")                                               \
                for (int nt = 0; nt < 4; nt++)                                  \
                    mma_bf16(acc[mt][nt], ahi[mt], bfr[nt]);                    \
        }                                                                       \
    }

// ---------------------------------------------------------------------------
// Merged Q/K/V projection GEMM (768 CTAs, runtime mode epilogues).
// bx<16: Q -> attention Q A-planes; bx in [16,20): K -> attention K B-planes;
// bx in [20,24): V -> fp32 g_V.
// ---------------------------------------------------------------------------
__global__ __launch_bounds__(256, 2)
void qkv_gemm(const __nv_bfloat16* __restrict__ aqh, const __nv_bfloat16* __restrict__ aql,
              const __nv_bfloat16* __restrict__ akh, const __nv_bfloat16* __restrict__ akl,
              const __nv_bfloat16* __restrict__ avh, const __nv_bfloat16* __restrict__ avl,
              const __nv_bfloat16* __restrict__ wqh, const __nv_bfloat16* __restrict__ wql,
              const __nv_bfloat16* __restrict__ wkh, const __nv_bfloat16* __restrict__ wkl,
              const __nv_bfloat16* __restrict__ wvh, const __nv_bfloat16* __restrict__ wvl,
              float* __restrict__ Vc,
              __nv_bfloat16* __restrict__ qaPh, __nv_bfloat16* __restrict__ qaPl,
              __nv_bfloat16* __restrict__ kbPh, __nv_bfloat16* __restrict__ kbPl)
{
    extern __shared__ char dsm[];
    const int tid  = threadIdx.x;
    const int lane = tid & 31;
    const int wid  = tid >> 5;
    const int warp_m = wid >> 2;
    const int warp_n = wid & 3;
    const int bx = blockIdx.x;
    const int mt0 = blockIdx.y;

    int mode, nt0;
    const __nv_bfloat16 *Ah, *Al, *Bh, *Bl;
    if (bx < 16)      { mode = 1; nt0 = bx;      Ah = aqh; Al = aql; Bh = wqh; Bl = wql; }
    else if (bx < 20) { mode = 2; nt0 = bx - 16; Ah = akh; Al = akl; Bh = wkh; Bl = wkl; }
    else              { mode = 0; nt0 = bx - 20; Ah = avh; Al = avl; Bh = wvh; Bl = wvl; }

    const char* pAh = (const char*)Ah + (size_t)mt0 * NCH * 4096;
    const char* pAl = (const char*)Al + (size_t)mt0 * NCH * 4096;
    const char* pBh = (const char*)Bh + (size_t)nt0 * NCH * 4096;
    const char* pBl = (const char*)Bl + (size_t)nt0 * NCH * 4096;

    float acc[4][4][4];
    GEMM_MAINLOOP();

    const int g  = lane >> 2;
    const int t4 = lane & 3;

    #pragma unroll
    for (int mt = 0; mt < 4; mt++) {
        #pragma unroll
        for (int nt = 0; nt < 4; nt++) {
            const int row0 = mt0 * 128 + warp_m * 64 + mt * 16 + g;
            const int col0 = nt0 * 128 + warp_n * 32 + nt * 8 + 2 * t4;

            if (mode == 0) {
                float* Cp = Vc + (size_t)row0 * PKVD + col0;
                *(float2*)(Cp)                    = make_float2(acc[mt][nt][0], acc[mt][nt][1]);
                *(float2*)(Cp + (size_t)8 * PKVD) = make_float2(acc[mt][nt][2], acc[mt][nt][3]);
            } else if (mode == 1) {
                const float scale = 0.08838834764831845f * 1.4426950408889634f;
                const int bb = row0 >> 11, s = row0 & 2047;
                const int qt = s >> 7, rr = s & 127;
                const int wq_ = rr >> 4;
                const int hh = col0 >> 7, d = col0 & 127;
                const int k16 = d >> 4, khi = (d >> 3) & 1;
                size_t base = (((((size_t)(bb * PH + hh) * 16 + qt) * 8 + wq_) * 8 + k16) * 512)
                            + (size_t)(g * 4 + t4) * 16;
                uint32_t uh0, ul0, uh1, ul1;
                split2(acc[mt][nt][0] * scale, acc[mt][nt][1] * scale, uh0, ul0);
                split2(acc[mt][nt][2] * scale, acc[mt][nt][3] * scale, uh1, ul1);
                *(uint32_t*)((char*)qaPh + base + (2 * khi) * 4)     = uh0;
                *(uint32_t*)((char*)qaPh + base + (1 + 2 * khi) * 4) = uh1;
                *(uint32_t*)((char*)qaPl + base + (2 * khi) * 4)     = ul0;
                *(uint32_t*)((char*)qaPl + base + (1 + 2 * khi) * 4) = ul1;
            } else {
                const int bb = row0 >> 11, s = row0 & 2047;
                const int kt = s >> 6, sk = s & 63;
                const int n8 = sk >> 3;
                const int gkv = col0 >> 7, d = col0 & 127;
                const int k16 = d >> 4, khi = (d >> 3) & 1;
                size_t base = ((size_t)(bb * PHKV + gkv) * 32 + kt) * 16384
                            + (size_t)(n8 * 4 + (k16 >> 1)) * 512
                            + (size_t)(g * 4 + t4) * 16 + (k16 & 1) * 8 + khi * 4;
                uint32_t uh0, ul0, uh1, ul1;
                split2(acc[mt][nt][0], acc[mt][nt][1], uh0, ul0);
                split2(acc[mt][nt][2], acc[mt][nt][3], uh1, ul1);
                *(uint32_t*)((char*)kbPh + base)        = uh0;
                *(uint32_t*)((char*)kbPh + base + 2048) = uh1;
                *(uint32_t*)((char*)kbPl + base)        = ul0;
                *(uint32_t*)((char*)kbPl + base + 2048) = ul1;
            }
        }
    }
}

// ---------------------------------------------------------------------------
// Plain GEMM for O-projection (fp32 C out)
// ---------------------------------------------------------------------------
__global__ __launch_bounds__(256, 2)
void tc_gemm0(const __nv_bfloat16* __restrict__ Ah, const __nv_bfloat16* __restrict__ Al,
              const __nv_bfloat16* __restrict__ Bh, const __nv_bfloat16* __restrict__ Bl,
              float* __restrict__ C, int N)
{
    extern __shared__ char dsm[];
    const int tid  = threadIdx.x;
    const int lane = tid & 31;
    const int wid  = tid >> 5;
    const int warp_m = wid >> 2;
    const int warp_n = wid & 3;
    const int mt0 = blockIdx.y, nt0 = blockIdx.x;

    const char* pAh = (const char*)Ah + (size_t)mt0 * NCH * 4096;
    const char* pAl = (const char*)Al + (size_t)mt0 * NCH * 4096;
    const char* pBh = (const char*)Bh + (size_t)nt0 * NCH * 4096;
    const char* pBl = (const char*)Bl + (size_t)nt0 * NCH * 4096;

    float acc[4][4][4];
    GEMM_MAINLOOP();

    const int g  = lane >> 2;
    const int t4 = lane & 3;
    #pragma unroll
    for (int mt = 0; mt < 4; mt++) {
        #pragma unroll
        for (int nt = 0; nt < 4; nt++) {
            const int row0 = mt0 * 128 + warp_m * 64 + mt * 16 + g;
            const int col0 = nt0 * 128 + warp_n * 32 + nt * 8 + 2 * t4;
            float* Cp = C + (size_t)row0 * N + col0;
            *(float2*)(Cp)                 = make_float2(acc[mt][nt][0], acc[mt][nt][1]);
            *(float2*)(Cp + (size_t)8 * N) = make_float2(acc[mt][nt][2], acc[mt][nt][3]);
        }
    }
}

// ---------------------------------------------------------------------------
// Tensor-core fused GQA flash attention (bf16-S3), base-2 softmax,
// paired-k16 LDS.128 fragment loads, conditional rescale, 3-stage pipeline.
// (unchanged from R12)
// ---------------------------------------------------------------------------
#define ATT_STG    65536
#define ATT_SMEM   (3 * ATT_STG)   // 196608

__global__ __launch_bounds__(256, 1)
void gqa_attn_mma(const __nv_bfloat16* __restrict__ Qh, const __nv_bfloat16* __restrict__ Ql,
                  const __nv_bfloat16* __restrict__ Kh, const __nv_bfloat16* __restrict__ Kl,
                  const __nv_bfloat16* __restrict__ Vh, const __nv_bfloat16* __restrict__ Vl,
                  const int* __restrict__ mask,
                  __nv_bfloat16* __restrict__ acPh, __nv_bfloat16* __restrict__ acPl)
{
    extern __shared__ char dsm[];
    const int tid  = threadIdx.x;
    const int lane = tid & 31;
    const int w    = tid >> 5;
    const int g    = lane >> 2;
    const int t4   = lane & 3;
    const int qt   = blockIdx.x;
    const int h    = blockIdx.y;
    const int b    = blockIdx.z;
    const int gkv  = h >> 2;

    uint32_t qh[8][4], ql[8][4];
    {
        const size_t qoff = (((((size_t)(b * PH + h) * 16 + qt) * 8 + w) * 8) * 512)
                          + (size_t)lane * 16;
        const char* qb  = (const char*)Qh + qoff;
        const char* qb2 = (const char*)Ql + qoff;
        #pragma unroll
        for (int k16 = 0; k16 < 8; k16++) {
            uint4 v = *(const uint4*)(qb + k16 * 512);
            qh[k16][0] = v.x; qh[k16][1] = v.y; qh[k16][2] = v.z; qh[k16][3] = v.w;
            uint4 u = *(const uint4*)(qb2 + k16 * 512);
            ql[k16][0] = u.x; ql[k16][1] = u.y; ql[k16][2] = u.z; ql[k16][3] = u.w;
        }
    }

    float oacc[16][4];
    #pragma unroll
    for (int n = 0; n < 16; n++)
        #pragma unroll
        for (int j = 0; j < 4; j++) oacc[n][j] = 0.0f;
    float m0 = -3.0e38f, m1 = -3.0e38f, l0 = 0.0f, l1 = 0.0f;

    const size_t kvPlane = ((size_t)(b * PHKV + gkv) * 32);
    const char* pKh = (const char*)Kh + kvPlane * 16384;
    const char* pKl = (const char*)Kl + kvPlane * 16384;
    const char* pVh = (const char*)Vh + kvPlane * 16384;
    const char* pVl = (const char*)Vl + kvPlane * 16384;

    const uint32_t sbase = smem_u32(dsm);
    const int t16 = tid * 16;

    #pragma unroll
    for (int s = 0; s < 2; s++) {
        const uint32_t dst = sbase + s * ATT_STG;
        const size_t go = (size_t)s * 16384;
        #pragma unroll
        for (int i = 0; i < 4; i++) {
            const int o = t16 + i * 4096;
            cp16(dst + o,         pKh + go + o);
            cp16(dst + 16384 + o, pKl + go + o);
            cp16(dst + 32768 + o, pVh + go + o);
            cp16(dst + 49152 + o, pVl + go + o);
        }
        asm volatile("cp.async.commit_group;" ::: "memory");
    }

    const int r0 = qt * 128 + w * 16 + g;
    const int r1 = r0 + 8;
    const int* mrow0 = mask + (size_t)(b * PS + r0) * PS;
    const int* mrow1 = mask + (size_t)(b * PS + r1) * PS;

    for (int kt = 0; kt < 32; kt++) {
        asm volatile("cp.async.wait_group 1;" ::: "memory");
        __syncthreads();

        if (kt + 2 < 32) {
            const uint32_t dst = sbase + ((kt + 2) % 3) * ATT_STG;
            const size_t go = (size_t)(kt + 2) * 16384;
            #pragma unroll
            for (int i = 0; i < 4; i++) {
                const int o = t16 + i * 4096;
                cp16(dst + o,         pKh + go + o);
                cp16(dst + 16384 + o, pKl + go + o);
                cp16(dst + 32768 + o, pVh + go + o);
                cp16(dst + 49152 + o, pVl + go + o);
            }
        }
        asm volatile("cp.async.commit_group;" ::: "memory");

        const char* stg = dsm + (kt % 3) * ATT_STG;
        const char* sKh = stg;
        const char* sKl = stg + 16384;
        const char* sVh = stg + 32768;
        const char* sVl = stg + 49152;

        float sm[8][4];
        #pragma unroll
        for (int n = 0; n < 8; n++)
            #pragma unroll
            for (int j = 0; j < 4; j++) sm[n][j] = 0.0f;

        #pragma unroll
        for (int kp = 0; kp < 4; kp++) {
            uint32_t be[8][2], bo[8][2];
            #pragma unroll
            for (int n = 0; n < 8; n++) {
                uint4 v = *(const uint4*)(sKh + (n * 4 + kp) * 512 + lane * 16);
                be[n][0] = v.x; be[n][1] = v.y; bo[n][0] = v.z; bo[n][1] = v.w;
            }
            #pragma unroll
            for (int n = 0; n < 8; n++) mma_bf16(sm[n], qh[2*kp],   be[n]);
            #pragma unroll
            for (int n = 0; n < 8; n++) mma_bf16(sm[n], qh[2*kp+1], bo[n]);
            #pragma unroll
            for (int n = 0; n < 8; n++) mma_bf16(sm[n], ql[2*kp],   be[n]);
            #pragma unroll
            for (int n = 0; n < 8; n++) mma_bf16(sm[n], ql[2*kp+1], bo[n]);
            #pragma unroll
            for (int n = 0; n < 8; n++) {
                uint4 u = *(const uint4*)(sKl + (n * 4 + kp) * 512 + lane * 16);
                be[n][0] = u.x; be[n][1] = u.y; bo[n][0] = u.z; bo[n][1] = u.w;
            }
            #pragma unroll
            for (int n = 0; n < 8; n++) mma_bf16(sm[n], qh[2*kp],   be[n]);
            #pragma unroll
            for (int n = 0; n < 8; n++) mma_bf16(sm[n], qh[2*kp+1], bo[n]);
        }

        const int kc0 = kt * 64 + 2 * t4;
        float mx0 = -3.0e38f, mx1 = -3.0e38f;
        #pragma unroll
        for (int n = 0; n < 8; n++) {
            int2 mv0 = *(const int2*)(mrow0 + kc0 + n * 8);
            int2 mv1 = *(const int2*)(mrow1 + kc0 + n * 8);
            sm[n][0] = mv0.x ? sm[n][0] : -1e9f;
            sm[n][1] = mv0.y ? sm[n][1] : -1e9f;
            sm[n][2] = mv1.x ? sm[n][2] : -1e9f;
            sm[n][3] = mv1.y ? sm[n][3] : -1e9f;
            mx0 = fmaxf(mx0, fmaxf(sm[n][0], sm[n][1]));
            mx1 = fmaxf(mx1, fmaxf(sm[n][2], sm[n][3]));
        }
        #pragma unroll
        for (int off = 1; off <= 2; off <<= 1) {
            mx0 = fmaxf(mx0, __shfl_xor_sync(0xffffffffu, mx0, off, 4));
            mx1 = fmaxf(mx1, __shfl_xor_sync(0xffffffffu, mx1, off, 4));
        }
        const float mn0 = fmaxf(m0, mx0);
        const float mn1 = fmaxf(m1, mx1);
        const float a0 = ex2f(m0 - mn0);
        const float a1 = ex2f(m1 - mn1);
        m0 = mn0; m1 = mn1;

        float rs0 = 0.0f, rs1 = 0.0f;
        #pragma unroll
        for (int n = 0; n < 8; n++) {
            sm[n][0] = ex2f(sm[n][0] - m0); rs0 += sm[n][0];
            sm[n][1] = ex2f(sm[n][1] - m0); rs0 += sm[n][1];
            sm[n][2] = ex2f(sm[n][2] - m1); rs1 += sm[n][2];
            sm[n][3] = ex2f(sm[n][3] - m1); rs1 += sm[n][3];
        }
        #pragma unroll
        for (int off = 1; off <= 2; off <<= 1) {
            rs0 += __shfl_xor_sync(0xffffffffu, rs0, off, 4);
            rs1 += __shfl_xor_sync(0xffffffffu, rs1, off, 4);
        }
        l0 = l0 * a0 + rs0;
        l1 = l1 * a1 + rs1;

        if (__any_sync(0xffffffffu, (a0 != 1.0f) || (a1 != 1.0f))) {
            #pragma unroll
            for (int n = 0; n < 16; n++) {
                oacc[n][0] *= a0; oacc[n][1] *= a0;
                oacc[n][2] *= a1; oacc[n][3] *= a1;
            }
        }

        #pragma unroll
        for (int kp = 0; kp < 2; kp++) {
            uint32_t phe[4], ple[4], pho[4], plo[4];
            split2(sm[4*kp][0],   sm[4*kp][1],   phe[0], ple[0]);
            split2(sm[4*kp][2],   sm[4*kp][3],   phe[1], ple[1]);
            split2(sm[4*kp+1][0], sm[4*kp+1][1], phe[2], ple[2]);
            split2(sm[4*kp+1][2], sm[4*kp+1][3], phe[3], ple[3]);
            split2(sm[4*kp+2][0], sm[4*kp+2][1], pho[0], plo[0]);
            split2(sm[4*kp+2][2], sm[4*kp+2][3], pho[1], plo[1]);
            split2(sm[4*kp+3][0], sm[4*kp+3][1], pho[2], plo[2]);
            split2(sm[4*kp+3][2], sm[4*kp+3][3], pho[3], plo[3]);

            #pragma unroll
            for (int ng = 0; ng < 4; ng++) {
                uint32_t ve[4][2], vo[4][2];
                #pragma unroll
                for (int j = 0; j < 4; j++) {
                    uint4 v = *(const uint4*)(sVh + ((ng*4 + j) * 2 + kp) * 512 + lane * 16);
                    ve[j][0] = v.x; ve[j][1] = v.y; vo[j][0] = v.z; vo[j][1] = v.w;
                }
                #pragma unroll
                for (int j = 0; j < 4; j++) mma_bf16(oacc[ng*4 + j], phe, ve[j]);
                #pragma unroll
                for (int j = 0; j < 4; j++) mma_bf16(oacc[ng*4 + j], pho, vo[j]);
                #pragma unroll
                for (int j = 0; j < 4; j++) mma_bf16(oacc[ng*4 + j], ple, ve[j]);
                #pragma unroll
                for (int j = 0; j < 4; j++) mma_bf16(oacc[ng*4 + j], plo, vo[j]);
            }
            #pragma unroll
            for (int ng = 0; ng < 4; ng++) {
                uint32_t ue[4][2], uo[4][2];
                #pragma unroll
                for (int j = 0; j < 4; j++) {
                    uint4 u = *(const uint4*)(sVl + ((ng*4 + j) * 2 + kp) * 512 + lane * 16);
                    ue[j][0] = u.x; ue[j][1] = u.y; uo[j][0] = u.z; uo[j][1] = u.w;
                }
                #pragma unroll
                for (int j = 0; j < 4; j++) mma_bf16(oacc[ng*4 + j], phe, ue[j]);
                #pragma unroll
                for (int j = 0; j < 4; j++) mma_bf16(oacc[ng*4 + j], pho, uo[j]);
            }
        }
    }

    const float inv0 = 1.0f / l0;
    const float inv1 = 1.0f / l1;
    const size_t cbase = (size_t)(b * 16 + qt) * NCH;
    #pragma unroll
    for (int n = 0; n < 16; n++) {
        const int c = h * 8 + (n >> 1);
        const size_t off = ((cbase + c) * 8 + w) * 512 + (size_t)(g * 4 + t4) * 16;
        uint32_t uh0, ul0, uh1, ul1;
        split2(oacc[n][0] * inv0, oacc[n][1] * inv0, uh0, ul0);
        split2(oacc[n][2] * inv1, oacc[n][3] * inv1, uh1, ul1);
        const int j0 = (2 * (n & 1)) * 4;
        const int j1 = (1 + 2 * (n & 1)) * 4;
        *(uint32_t*)((char*)acPh + off + j0) = uh0;
        *(uint32_t*)((char*)acPh + off + j1) = uh1;
        *(uint32_t*)((char*)acPl + off + j0) = ul0;
        *(uint32_t*)((char*)acPl + off + j1) = ul1;
    }
}

// ---------------------------------------------------------------------------
// Launch
// ---------------------------------------------------------------------------
extern "C" void kernel_launch(void* const* d_in, const int* in_sizes, int n_in,
                              void* d_out, int out_size)
{
    (void)in_sizes; (void)n_in; (void)out_size;
    const float* query = (const float*)d_in[0];
    const float* key   = (const float*)d_in[1];
    const float* value = (const float*)d_in[2];
    const int*   mask  = (const int*)  d_in[3];
    const float* Wq    = (const float*)d_in[4];
    const float* Wk    = (const float*)d_in[5];
    const float* Wv    = (const float*)d_in[6];
    const float* Wo    = (const float*)d_in[7];
    float* out = (float*)d_out;

    float* pV;
    cudaGetSymbolAddress((void**)&pV, g_V);

    __nv_bfloat16 *aq_h, *aq_l, *ak_h, *ak_l, *av_h, *av_l, *ac_h, *ac_l;
    __nv_bfloat16 *wq_h, *wq_l, *wk_h, *wk_l, *wv_h, *wv_l, *wo_h, *wo_l;
    __nv_bfloat16 *qa_h, *qa_l, *kb_h, *kb_l, *vb_h, *vb_l;
    cudaGetSymbolAddress((void**)&aq_h, g_aq_h); cudaGetSymbolAddress((void**)&aq_l, g_aq_l);
    cudaGetSymbolAddress((void**)&ak_h, g_ak_h); cudaGetSymbolAddress((void**)&ak_l, g_ak_l);
    cudaGetSymbolAddress((void**)&av_h, g_av_h); cudaGetSymbolAddress((void**)&av_l, g_av_l);
    cudaGetSymbolAddress((void**)&ac_h, g_ac_h); cudaGetSymbolAddress((void**)&ac_l, g_ac_l);
    cudaGetSymbolAddress((void**)&wq_h, g_wq_h); cudaGetSymbolAddress((void**)&wq_l, g_wq_l);
    cudaGetSymbolAddress((void**)&wk_h, g_wk_h); cudaGetSymbolAddress((void**)&wk_l, g_wk_l);
    cudaGetSymbolAddress((void**)&wv_h, g_wv_h); cudaGetSymbolAddress((void**)&wv_l, g_wv_l);
    cudaGetSymbolAddress((void**)&wo_h, g_wo_h); cudaGetSymbolAddress((void**)&wo_l, g_wo_l);
    cudaGetSymbolAddress((void**)&qa_h, g_qa_h); cudaGetSymbolAddress((void**)&qa_l, g_qa_l);
    cudaGetSymbolAddress((void**)&kb_h, g_kb_h); cudaGetSymbolAddress((void**)&kb_l, g_kb_l);
    cudaGetSymbolAddress((void**)&vb_h, g_vb_h); cudaGetSymbolAddress((void**)&vb_l, g_vb_l);

    cudaFuncSetAttribute(qkv_gemm, cudaFuncAttributeMaxDynamicSharedMemorySize, GEMM_SMEM);
    cudaFuncSetAttribute(tc_gemm0, cudaFuncAttributeMaxDynamicSharedMemorySize, GEMM_SMEM);
    cudaFuncSetAttribute(gqa_attn_mma, cudaFuncAttributeMaxDynamicSharedMemorySize, ATT_SMEM);

    // Pack weights
    pack_wT<<<dim3(PD / 32, PD / 32),   dim3(32, 8)>>>(Wq, wq_h, wq_l, PD);
    pack_wT<<<dim3(PKVD / 32, PD / 32), dim3(32, 8)>>>(Wk, wk_h, wk_l, PKVD);
    pack_wT<<<dim3(PKVD / 32, PD / 32), dim3(32, 8)>>>(Wv, wv_h, wv_l, PKVD);
    pack_wT<<<dim3(PD / 32, PD / 32),   dim3(32, 8)>>>(Wo, wo_h, wo_l, PD);

    // Pack all three input activations in one launch
    pack_a3<<<3 * PACKA_BLOCKS_PER, 256>>>(query, key, value,
                                           aq_h, aq_l, ak_h, ak_l, av_h, av_l);

    // Merged Q/K/V projections (one launch, 768 CTAs)
    qkv_gemm<<<dim3(24, PM / 128), 256, GEMM_SMEM>>>(
        aq_h, aq_l, ak_h, ak_l, av_h, av_l,
        wq_h, wq_l, wk_h, wk_l, wv_h, wv_l,
        pV, qa_h, qa_l, kb_h, kb_l);

    pack_vb<<<(PM / 2 * PKVD) / 256, 256>>>(pV, vb_h, vb_l);

    // Tensor-core fused attention — writes O-proj A-planes directly
    gqa_attn_mma<<<dim3(PS / 128, PH, PB), 256, ATT_SMEM>>>(
        qa_h, qa_l, kb_h, kb_l, vb_h, vb_l, mask, ac_h, ac_l);

    // Output projection
    tc_gemm0<<<dim3(PD / 128, PM / 128), 256, GEMM_SMEM>>>(
        ac_h, ac_l, wo_h, wo_l, out, PD);
}